// round 12
// baseline (speedup 1.0000x reference)
#include <cuda_runtime.h>
#include <cuda_fp16.h>
#include <math.h>
#include <stdint.h>

// ---------------------------------------------------------------------------
// LatentMixer on GB300 (sm_103 plain target): single-term fp16 HMMA GEMMs,
// fused attention, half-batch overlap of proj GEMM with attention chain.
// B=8, C=512, N=4096, heads=8, d=64, L=16, scale=0.125
// ---------------------------------------------------------------------------

#define Bsz 8
#define C   512
#define NPIX 4096
#define L   16
#define HEADS 8
#define DH  64
#define SCALE 0.125f
#define EPSN 1e-12f
#define KDIM 512
#define MROWS 1536   // stacked k(512) v(512) q(512)

// ---------------- scratch (device globals; allocation-free contract) -------
__device__ __half g_kvq[(size_t)Bsz * MROWS * NPIX];   // fp16 k/v/q
__device__ float g_lsum[64 * 4 * L];
__device__ float g_latpart[4 * 64 * DH * L];
__device__ float g_kvl[Bsz * 2 * C * L];
__device__ float g_qlhat[C * L];
__device__ __half g_xT [(size_t)Bsz * NPIX * C];       // x transposed fp16
__device__ __half g_xwT[(size_t)Bsz * NPIX * C];       // attn2 out fp16
__device__ __half g_wA[MROWS * KDIM];                  // stacked w_kv_x ; w_q_x
__device__ __half g_wp[C * KDIM];                      // w_proj

// ---------------- helpers ---------------------------------------------------
__device__ __forceinline__ uint32_t smem_u32(const void* p) {
    uint32_t a;
    asm("{ .reg .u64 t; cvta.to.shared.u64 t, %1; cvt.u32.u64 %0, t; }" : "=r"(a) : "l"(p));
    return a;
}

#define LDSM4(r, addr) \
    asm volatile("ldmatrix.sync.aligned.m8n8.x4.shared.b16 {%0,%1,%2,%3}, [%4];" \
                 : "=r"((r)[0]), "=r"((r)[1]), "=r"((r)[2]), "=r"((r)[3]) : "r"(addr))

#define MMA16816(cc, aa, b0, b1) \
    asm volatile("mma.sync.aligned.m16n8k16.row.col.f32.f16.f16.f32 " \
                 "{%0,%1,%2,%3}, {%4,%5,%6,%7}, {%8,%9}, {%0,%1,%2,%3};" \
                 : "+f"((cc)[0]), "+f"((cc)[1]), "+f"((cc)[2]), "+f"((cc)[3]) \
                 : "r"((aa)[0]), "r"((aa)[1]), "r"((aa)[2]), "r"((aa)[3]), \
                   "r"(b0), "r"(b1))

#define CP_ASYNC16(dst, src) \
    asm volatile("cp.async.cg.shared.global [%0], [%1], 16;" :: "r"(dst), "l"(src))
#define CP_COMMIT() asm volatile("cp.async.commit_group;" ::: "memory")
#define CP_WAIT(n)  asm volatile("cp.async.wait_group %0;" :: "n"(n) : "memory")

// ---------------------------------------------------------------------------
// Fused weight convert for wA: w_kv_x (1024x512) ; w_q_x (512x512) -> fp16
// ---------------------------------------------------------------------------
#define KV4 (2 * C * KDIM / 4)
#define Q4  (C * KDIM / 4)
__global__ __launch_bounds__(256) void wconvA_kernel(
    const float* __restrict__ wkv, const float* __restrict__ wq,
    __half* __restrict__ wA)
{
    int i = blockIdx.x * 256 + threadIdx.x;
    if (i >= KV4 + Q4) return;
    const float* src = (i < KV4) ? (wkv + i * 4) : (wq + (i - KV4) * 4);
    float4 v = *(const float4*)src;
    __half2* o = (__half2*)(wA + i * 4);
    o[0] = __floats2half2_rn(v.x, v.y);
    o[1] = __floats2half2_rn(v.z, v.w);
}

__global__ __launch_bounds__(256) void wconv_kernel(
    const float* __restrict__ a, __half* __restrict__ hi, int n4)
{
    int i = blockIdx.x * 256 + threadIdx.x;
    if (i >= n4) return;
    float4 v = ((const float4*)a)[i];
    __half2* o = (__half2*)(hi + i * 4);
    o[0] = __floats2half2_rn(v.x, v.y);
    o[1] = __floats2half2_rn(v.z, v.w);
}

// ---------------------------------------------------------------------------
// Transpose x: [B,C,N] fp32 -> [B,N,C] fp16. 32x32 tiles.
// ---------------------------------------------------------------------------
__global__ __launch_bounds__(256) void tconv_kernel(
    const float* __restrict__ x, __half* __restrict__ xo)
{
    __shared__ float t[32][33];
    int n0 = blockIdx.x * 32, c0 = blockIdx.y * 32, b = blockIdx.z;
    int tx = threadIdx.x, ty = threadIdx.y;
    const float* xb = x + (size_t)b * C * NPIX;
    #pragma unroll
    for (int i = 0; i < 4; i++)
        t[ty + i * 8][tx] = xb[(size_t)(c0 + ty + i * 8) * NPIX + n0 + tx];
    __syncthreads();
    __half* ob = xo + (size_t)b * NPIX * C;
    #pragma unroll
    for (int i = 0; i < 4; i++)
        ob[(size_t)(n0 + ty + i * 8) * C + c0 + tx] = __float2half_rn(t[tx][ty + i * 8]);
}

// ---------------------------------------------------------------------------
// HMMA GEMM: C[z][m][n] = sum_k A[m][k]*B[z][n][k], single fp16 term.
// Tile 128x128x64, 256 threads (2x4 warps), 3-stage cp.async, 2 CTAs/SM.
// Output: fp16 (Ch) or fp32+bias (Cf); per-z stride = M*NPIX.
// ---------------------------------------------------------------------------
#define STG 32768
__device__ __forceinline__ void gemm_load_stage(
    char* sm, int stg, int ck, int tid,
    const __half* a0, const __half* b0)
{
    char* d = sm + stg * STG;
    #pragma unroll
    for (int i = 0; i < 8; i++) {
        int u = tid + i * 256;
        int r = u >> 10, idx = u & 1023, row = idx >> 3, c = idx & 7;
        const __half* src = ((r == 0) ? a0 : b0) + (size_t)row * KDIM + ck * 64 + c * 8;
        uint32_t dst = smem_u32(d + r * 16384 + row * 128 + (((c ^ (row & 7))) << 4));
        CP_ASYNC16(dst, src);
    }
    CP_COMMIT();
}

__global__ __launch_bounds__(256, 2) void gemm_mma(
    const __half* __restrict__ A, const __half* __restrict__ B,
    __half* __restrict__ Ch, float* __restrict__ Cf,
    const float* __restrict__ bias, int M)
{
    extern __shared__ char sm[];
    int tid = threadIdx.x, lane = tid & 31, wid = tid >> 5;
    int wm = wid >> 2, wn = wid & 3;
    int m0 = blockIdx.y * 128, n0 = blockIdx.x * 128, z = blockIdx.z;

    const __half* a0p = A + (size_t)m0 * KDIM;
    const __half* b0p = B + ((size_t)z * NPIX + n0) * KDIM;

    float acc[4][4][4];
    #pragma unroll
    for (int i = 0; i < 4; i++)
        #pragma unroll
        for (int j = 0; j < 4; j++)
            #pragma unroll
            for (int k = 0; k < 4; k++) acc[i][j][k] = 0.f;

    gemm_load_stage(sm, 0, 0, tid, a0p, b0p);
    gemm_load_stage(sm, 1, 1, tid, a0p, b0p);

    int a_row = wm * 64 + ((lane >> 3) & 1) * 8 + (lane & 7);
    int a_ck  = (lane >> 4);
    int b_row = wn * 32 + (lane >> 4) * 8 + (lane & 7);
    int b_ck  = ((lane >> 3) & 1);
    uint32_t sbase = smem_u32(sm);

    for (int ck = 0; ck < 8; ck++) {
        if (ck + 2 < 8) {
            gemm_load_stage(sm, (ck + 2) % 3, ck + 2, tid, a0p, b0p);
            CP_WAIT(2);
        } else if (ck + 1 < 8) {
            CP_WAIT(1);
        } else {
            CP_WAIT(0);
        }
        __syncthreads();

        uint32_t st = sbase + (ck % 3) * STG;
        #pragma unroll
        for (int kk = 0; kk < 4; kk++) {
            uint32_t af[4][4];
            #pragma unroll
            for (int mf = 0; mf < 4; mf++) {
                int row = a_row + mf * 16;
                int chv = (kk * 2 + a_ck) ^ (row & 7);
                LDSM4(af[mf], st + row * 128 + (chv << 4));
            }
            uint32_t bf[2][4];
            #pragma unroll
            for (int ng = 0; ng < 2; ng++) {
                int row = b_row + ng * 16;
                int chv = (kk * 2 + b_ck) ^ (row & 7);
                LDSM4(bf[ng], st + 16384 + row * 128 + (chv << 4));
            }
            #pragma unroll
            for (int mf = 0; mf < 4; mf++)
                #pragma unroll
                for (int ng = 0; ng < 2; ng++)
                    #pragma unroll
                    for (int nh = 0; nh < 2; nh++)
                        MMA16816(acc[mf][ng * 2 + nh], af[mf],
                                 bf[ng][nh * 2], bf[ng][nh * 2 + 1]);
        }
        __syncthreads();
    }

    size_t obase = (size_t)z * M * NPIX;
    if (Ch) {
        #pragma unroll
        for (int mf = 0; mf < 4; mf++) {
            int m = m0 + wm * 64 + mf * 16 + (lane >> 2);
            #pragma unroll
            for (int nf = 0; nf < 4; nf++) {
                int n = n0 + wn * 32 + nf * 8 + (lane & 3) * 2;
                *(__half2*)&Ch[obase + (size_t)m * NPIX + n] =
                    __floats2half2_rn(acc[mf][nf][0], acc[mf][nf][1]);
                *(__half2*)&Ch[obase + (size_t)(m + 8) * NPIX + n] =
                    __floats2half2_rn(acc[mf][nf][2], acc[mf][nf][3]);
            }
        }
    } else {
        #pragma unroll
        for (int mf = 0; mf < 4; mf++) {
            int m = m0 + wm * 64 + mf * 16 + (lane >> 2);
            float bb0 = bias ? bias[m] : 0.f;
            float bb8 = bias ? bias[m + 8] : 0.f;
            #pragma unroll
            for (int nf = 0; nf < 4; nf++) {
                int n = n0 + wn * 32 + nf * 8 + (lane & 3) * 2;
                *(float2*)&Cf[obase + (size_t)m * NPIX + n] =
                    make_float2(acc[mf][nf][0] + bb0, acc[mf][nf][1] + bb0);
                *(float2*)&Cf[obase + (size_t)(m + 8) * NPIX + n] =
                    make_float2(acc[mf][nf][2] + bb8, acc[mf][nf][3] + bb8);
            }
        }
    }
}

// ---------------------------------------------------------------------------
// qlhat: normalized latent queries (batch-invariant). grid=8, 256 threads.
// ---------------------------------------------------------------------------
__global__ __launch_bounds__(256) void qlhat_kernel(
    const float* __restrict__ w_q_lat, const float* __restrict__ latents,
    float* __restrict__ qlhat)
{
    int h = blockIdx.x;
    __shared__ float slat[C][L];
    __shared__ float stile[DH][L];
    __shared__ float snorm[L];
    int tid = threadIdx.x;
    for (int i = tid; i < C * L; i += 256) slat[i >> 4][i & 15] = latents[i];
    __syncthreads();
    for (int p = tid; p < DH * L; p += 256) {
        int j = p >> 4, l = p & 15;
        const float* wrow = w_q_lat + (size_t)(h * DH + j) * C;
        float acc = 0.f;
        for (int c2 = 0; c2 < C; c2++) acc += wrow[c2] * slat[c2][l];
        stile[j][l] = acc;
    }
    __syncthreads();
    if (tid < L) {
        float s = 0.f;
        for (int j = 0; j < DH; j++) { float v = stile[j][tid]; s += v * v; }
        snorm[tid] = 1.f / fmaxf(sqrtf(s), EPSN);
    }
    __syncthreads();
    for (int p = tid; p < DH * L; p += 256)
        qlhat[(h * DH + (p >> 4)) * L + (p & 15)] = stile[p >> 4][p & 15] * snorm[p & 15];
}

// ---------------------------------------------------------------------------
// attn1 fused: per (bh0+bx, split of 1024 px): exp -> smem tile, L-sums,
// unnormalized partial P@V. grid (nbh, 4), 512 threads, ~69KB dynamic smem.
// ---------------------------------------------------------------------------
__global__ __launch_bounds__(512) void attn1_fused_kernel(
    const __half* __restrict__ kvq, const float* __restrict__ qlhat,
    float* __restrict__ latpart, float* __restrict__ lsum_g, int bh0)
{
    extern __shared__ float dyn[];
    float* p_sm = dyn;                       // [16][1024] = 64KB
    float (*sql)[L] = (float(*)[L])(dyn + L * 1024);
    float (*wred)[L] = (float(*)[L])(dyn + L * 1024 + DH * L);

    int bh = bh0 + blockIdx.x, split = blockIdx.y, b = bh >> 3, h = bh & 7;
    const __half* kbase = kvq + ((size_t)b * MROWS + h * DH) * NPIX + split * 1024;
    const __half* vbase = kvq + ((size_t)b * MROWS + 512 + h * DH) * NPIX + split * 1024;
    int tid = threadIdx.x, lane = tid & 31, wrp = tid >> 5;

    for (int i = tid; i < DH * L; i += 512)
        sql[i >> 4][i & 15] = qlhat[(h * DH + (i >> 4)) * L + (i & 15)];
    __syncthreads();

    {
        float dot[2][L], nrm[2] = {0.f, 0.f};
        #pragma unroll
        for (int i = 0; i < 2; i++)
            #pragma unroll
            for (int l = 0; l < L; l++) dot[i][l] = 0.f;
        for (int j = 0; j < DH; j++) {
            __half2 a01 = *(const __half2*)(kbase + (size_t)j * NPIX + 2 * tid);
            float k0 = __low2float(a01), k1 = __high2float(a01);
            nrm[0] += k0 * k0; nrm[1] += k1 * k1;
            #pragma unroll
            for (int l = 0; l < L; l++) {
                float s = sql[j][l];
                dot[0][l] += k0 * s;
                dot[1][l] += k1 * s;
            }
        }
        float inv0 = SCALE / fmaxf(sqrtf(nrm[0]), EPSN);
        float inv1 = SCALE / fmaxf(sqrtf(nrm[1]), EPSN);
        float lsum[L];
        #pragma unroll
        for (int l = 0; l < L; l++) {
            float p0 = __expf(dot[0][l] * inv0);
            float p1 = __expf(dot[1][l] * inv1);
            lsum[l] = p0 + p1;
            *(float2*)&p_sm[l * 1024 + 2 * tid] = make_float2(p0, p1);
        }
        #pragma unroll
        for (int l = 0; l < L; l++) {
            float v = lsum[l];
            #pragma unroll
            for (int o = 16; o; o >>= 1) v += __shfl_xor_sync(0xffffffffu, v, o);
            if (lane == 0) wred[wrp][l] = v;
        }
    }
    __syncthreads();
    if (tid < L) {
        float s = 0.f;
        #pragma unroll
        for (int w = 0; w < 16; w++) s += wred[w][tid];
        lsum_g[bh * 64 + split * 16 + tid] = s;
    }

    float acc[4][L];
    #pragma unroll
    for (int jj = 0; jj < 4; jj++)
        #pragma unroll
        for (int l = 0; l < L; l++) acc[jj][l] = 0.f;

    for (int it = 0; it < 16; it++) {
        int n2 = it * 64 + lane * 2;
        float2 pv[L];
        #pragma unroll
        for (int l = 0; l < L; l++) pv[l] = *(const float2*)&p_sm[l * 1024 + n2];
        #pragma unroll
        for (int jj = 0; jj < 4; jj++) {
            __half2 v2 = *(const __half2*)&vbase[(size_t)(wrp * 4 + jj) * NPIX + n2];
            float v0 = __low2float(v2), v1 = __high2float(v2);
            #pragma unroll
            for (int l = 0; l < L; l++) acc[jj][l] += v0 * pv[l].x + v1 * pv[l].y;
        }
    }
    #pragma unroll
    for (int jj = 0; jj < 4; jj++)
        #pragma unroll
        for (int l = 0; l < L; l++) {
            float v = acc[jj][l];
            #pragma unroll
            for (int o = 16; o; o >>= 1) v += __shfl_xor_sync(0xffffffffu, v, o);
            if (lane == 0)
                latpart[split * 65536 + bh * 1024 + (wrp * 4 + jj) * 16 + l] = v;
        }
}

// ---------------------------------------------------------------------------
// kvl (attn1d fused): reconstruct latread[b] from latpart/lsum inline, then
// kvl[b] = w_kv_lat @ latread; normalize k-part. grid (nb, 16), 256 threads.
// ---------------------------------------------------------------------------
__global__ __launch_bounds__(256) void kvl_kernel(
    const float* __restrict__ w_kv_lat, const float* __restrict__ latpart,
    const float* __restrict__ lsum_g, float* __restrict__ kvl, int b0)
{
    int b = b0 + blockIdx.x, c0 = blockIdx.y * 64;
    __shared__ float slat[C][L];
    __shared__ float stile[64][L];
    __shared__ float snorm[L];
    int tid = threadIdx.x;
    for (int i = tid; i < C * L; i += 256) {
        int c = i >> 4, l = i & 15;
        int h = c >> 6, r = c & 63;
        int bh = b * 8 + h;
        int e = bh * 1024 + r * 16 + l;
        float s = latpart[e] + latpart[65536 + e] + latpart[131072 + e] + latpart[196608 + e];
        float d = lsum_g[bh * 64 + l] + lsum_g[bh * 64 + 16 + l] +
                  lsum_g[bh * 64 + 32 + l] + lsum_g[bh * 64 + 48 + l];
        slat[c][l] = s / d;
    }
    __syncthreads();
    for (int p = tid; p < 64 * L; p += 256) {
        int j = p >> 4, l = p & 15;
        const float* wrow = w_kv_lat + (size_t)(c0 + j) * C;
        float acc = 0.f;
        for (int c2 = 0; c2 < C; c2++) acc += wrow[c2] * slat[c2][l];
        stile[j][l] = acc;
    }
    __syncthreads();
    if (c0 < C) {
        if (tid < L) {
            float s = 0.f;
            for (int j = 0; j < 64; j++) { float v = stile[j][tid]; s += v * v; }
            snorm[tid] = 1.f / fmaxf(sqrtf(s), EPSN);
        }
        __syncthreads();
        for (int p = tid; p < 64 * L; p += 256)
            kvl[((size_t)b * 2 * C + c0 + (p >> 4)) * L + (p & 15)] =
                stile[p >> 4][p & 15] * snorm[p & 15];
    } else {
        for (int p = tid; p < 64 * L; p += 256)
            kvl[((size_t)b * 2 * C + c0 + (p >> 4)) * L + (p & 15)] = stile[p >> 4][p & 15];
    }
}

// ---------------------------------------------------------------------------
// attn2: 2 pixels/thread via half2 q loads; fp16 xwT out.
// grid (16, HEADS, nb), 128 threads.
// ---------------------------------------------------------------------------
__global__ __launch_bounds__(128) void attn2_kernel(
    const __half* __restrict__ kvq, const float* __restrict__ kvl,
    __half* __restrict__ xwT, int b0)
{
    int b = b0 + blockIdx.z, h = blockIdx.y;
    int tid = threadIdx.x;
    int n = blockIdx.x * 256 + 2 * tid;
    __shared__ float skl[DH][L];
    __shared__ float svl[DH][L];
    __shared__ unsigned short sh[DH][256];

    const float* kvlb = kvl + (size_t)b * 2 * C * L;
    for (int i = tid; i < DH * L; i += 128) {
        skl[i >> 4][i & 15] = kvlb[(h * DH + (i >> 4)) * L + (i & 15)];
        svl[i >> 4][i & 15] = kvlb[(C + h * DH + (i >> 4)) * L + (i & 15)];
    }
    __syncthreads();

    const __half* qcol = kvq + ((size_t)b * MROWS + 1024 + h * DH) * NPIX + n;
    float dot[2][L], nrm[2] = {0.f, 0.f};
    #pragma unroll
    for (int i = 0; i < 2; i++)
        #pragma unroll
        for (int l = 0; l < L; l++) dot[i][l] = 0.f;
    for (int j = 0; j < DH; j++) {
        __half2 q2 = *(const __half2*)(qcol + (size_t)j * NPIX);
        float q0 = __low2float(q2), q1 = __high2float(q2);
        nrm[0] += q0 * q0; nrm[1] += q1 * q1;
        #pragma unroll
        for (int l = 0; l < L; l++) {
            float s = skl[j][l];
            dot[0][l] += q0 * s;
            dot[1][l] += q1 * s;
        }
    }
    float is[2];
    #pragma unroll
    for (int i = 0; i < 2; i++) {
        float inv = SCALE / fmaxf(sqrtf(nrm[i]), EPSN);
        float s = 0.f;
        #pragma unroll
        for (int l = 0; l < L; l++) { dot[i][l] = __expf(dot[i][l] * inv); s += dot[i][l]; }
        is[i] = 1.f / s;
    }

    for (int j = 0; j < DH; j++) {
        float a0 = 0.f, a1 = 0.f;
        #pragma unroll
        for (int l = 0; l < L; l++) {
            float v = svl[j][l];
            a0 += dot[0][l] * v;
            a1 += dot[1][l] * v;
        }
        sh[j][2 * tid]     = __half_as_ushort(__float2half_rn(a0 * is[0]));
        sh[j][2 * tid + 1] = __half_as_ushort(__float2half_rn(a1 * is[1]));
    }
    __syncthreads();

    #pragma unroll
    for (int px = 0; px < 2; px++) {
        int pp = 2 * tid + px;
        int np = blockIdx.x * 256 + pp;
        size_t base = ((size_t)b * NPIX + np) * C + h * DH;
        #pragma unroll
        for (int c4 = 0; c4 < 8; c4++) {
            uint32_t wv[4];
            #pragma unroll
            for (int k = 0; k < 4; k++) {
                int j = c4 * 8 + k * 2;
                wv[k] = (uint32_t)sh[j][pp] | ((uint32_t)sh[j + 1][pp] << 16);
            }
            *(uint4*)(xwT + base + c4 * 8) = make_uint4(wv[0], wv[1], wv[2], wv[3]);
        }
    }
}

// ---------------------------------------------------------------------------
// Launch: R8 topology + half-batch attn/proj overlap.
//   s1: wA conv (evA); s2: wp conv + qlhat (evSide)
//   main: tconv, gemm_kvq (evG), then proj(h0) after evX0, proj(h1) after evX1
//   s4: after evG+evSide: attn chain h0 (evX0), attn chain h1 (evX1)
// ---------------------------------------------------------------------------
extern "C" void kernel_launch(void* const* d_in, const int* in_sizes, int n_in,
                              void* d_out, int out_size)
{
    const float* x        = (const float*)d_in[0];
    const float* latents  = (const float*)d_in[1];
    const float* w_q_lat  = (const float*)d_in[2];
    const float* w_kv_x   = (const float*)d_in[3];
    const float* w_q_x    = (const float*)d_in[4];
    const float* w_kv_lat = (const float*)d_in[5];
    const float* w_proj   = (const float*)d_in[6];
    const float* b_proj   = (const float*)d_in[7];
    float* out = (float*)d_out;

    float *lsum, *latpart, *kvl, *qlhat;
    __half *kvq, *xT, *xwT, *wA, *wp;
    cudaGetSymbolAddress((void**)&kvq, g_kvq);
    cudaGetSymbolAddress((void**)&lsum, g_lsum);
    cudaGetSymbolAddress((void**)&latpart, g_latpart);
    cudaGetSymbolAddress((void**)&kvl, g_kvl);
    cudaGetSymbolAddress((void**)&qlhat, g_qlhat);
    cudaGetSymbolAddress((void**)&xT, g_xT);
    cudaGetSymbolAddress((void**)&xwT, g_xwT);
    cudaGetSymbolAddress((void**)&wA, g_wA);
    cudaGetSymbolAddress((void**)&wp, g_wp);

    static cudaStream_t s1 = nullptr, s2 = nullptr, s4 = nullptr;
    static cudaEvent_t evFork = nullptr, evA = nullptr, evSide = nullptr,
                       evG = nullptr, evX0 = nullptr, evX1 = nullptr;
    if (!s1) {
        cudaStreamCreateWithFlags(&s1, cudaStreamNonBlocking);
        cudaStreamCreateWithFlags(&s2, cudaStreamNonBlocking);
        cudaStreamCreateWithFlags(&s4, cudaStreamNonBlocking);
        cudaEventCreateWithFlags(&evFork, cudaEventDisableTiming);
        cudaEventCreateWithFlags(&evA, cudaEventDisableTiming);
        cudaEventCreateWithFlags(&evSide, cudaEventDisableTiming);
        cudaEventCreateWithFlags(&evG, cudaEventDisableTiming);
        cudaEventCreateWithFlags(&evX0, cudaEventDisableTiming);
        cudaEventCreateWithFlags(&evX1, cudaEventDisableTiming);
    }

    cudaFuncSetAttribute(gemm_mma, cudaFuncAttributeMaxDynamicSharedMemorySize, 3 * STG);
    int attn1_smem = (L * 1024 + DH * L + 16 * L) * sizeof(float);
    cudaFuncSetAttribute(attn1_fused_kernel, cudaFuncAttributeMaxDynamicSharedMemorySize, attn1_smem);

    cudaEventRecord(evFork, 0);
    // s1: fused kv+q weight conversion
    cudaStreamWaitEvent(s1, evFork, 0);
    wconvA_kernel<<<(KV4 + Q4 + 255) / 256, 256, 0, s1>>>(w_kv_x, w_q_x, wA);
    cudaEventRecord(evA, s1);
    // s2: proj weight conversion + qlhat
    cudaStreamWaitEvent(s2, evFork, 0);
    wconv_kernel<<<(Q4 + 255) / 256, 256, 0, s2>>>(w_proj, wp, Q4);
    qlhat_kernel<<<HEADS, 256, 0, s2>>>(w_q_lat, latents, qlhat);
    cudaEventRecord(evSide, s2);

    // main: transpose x, fused kv+q GEMM (all batches)
    tconv_kernel<<<dim3(NPIX / 32, C / 32, Bsz), dim3(32, 8)>>>(x, xT);
    cudaStreamWaitEvent(0, evA, 0);
    gemm_mma<<<dim3(32, 12, Bsz), 256, 3 * STG>>>(wA, xT, kvq, nullptr, nullptr, MROWS);
    cudaEventRecord(evG, 0);

    // s4: attention chain, two half-batches
    cudaStreamWaitEvent(s4, evG, 0);
    cudaStreamWaitEvent(s4, evSide, 0);
    attn1_fused_kernel<<<dim3(32, 4), 512, attn1_smem, s4>>>(kvq, qlhat, latpart, lsum, 0);
    kvl_kernel<<<dim3(4, 16), 256, 0, s4>>>(w_kv_lat, latpart, lsum, kvl, 0);
    attn2_kernel<<<dim3(16, HEADS, 4), 128, 0, s4>>>(kvq, kvl, xwT, 0);
    cudaEventRecord(evX0, s4);
    attn1_fused_kernel<<<dim3(32, 4), 512, attn1_smem, s4>>>(kvq, qlhat, latpart, lsum, 32);
    kvl_kernel<<<dim3(4, 16), 256, 0, s4>>>(w_kv_lat, latpart, lsum, kvl, 4);
    attn2_kernel<<<dim3(16, HEADS, 4), 128, 0, s4>>>(kvq, kvl, xwT, 4);
    cudaEventRecord(evX1, s4);

    // main: proj halves (overlap proj(h0) with attn chain h1)
    cudaStreamWaitEvent(0, evSide, 0);
    cudaStreamWaitEvent(0, evX0, 0);
    gemm_mma<<<dim3(32, 4, 4), 256, 3 * STG>>>(wp, xwT, nullptr, out, b_proj, C);
    cudaStreamWaitEvent(0, evX1, 0);
    gemm_mma<<<dim3(32, 4, 4), 256, 3 * STG>>>(wp, xwT + (size_t)4 * NPIX * C, nullptr,
                                               out + (size_t)4 * C * NPIX, b_proj, C);
}

// round 14
// speedup vs baseline: 1.4223x; 1.4223x over previous
#include <cuda_runtime.h>
#include <cuda_fp16.h>
#include <math.h>
#include <stdint.h>

// ---------------------------------------------------------------------------
// LatentMixer on GB300 (sm_103 plain target): single-term fp16 HMMA GEMMs,
// fused attention. R8 stream topology (proven fastest) + fused kvl + fast tconv.
// B=8, C=512, N=4096, heads=8, d=64, L=16, scale=0.125
// ---------------------------------------------------------------------------

#define Bsz 8
#define C   512
#define NPIX 4096
#define L   16
#define HEADS 8
#define DH  64
#define SCALE 0.125f
#define EPSN 1e-12f
#define KDIM 512
#define MROWS 1536   // stacked k(512) v(512) q(512)

// ---------------- scratch (device globals; allocation-free contract) -------
__device__ __half g_kvq[(size_t)Bsz * MROWS * NPIX];   // fp16 k/v/q
__device__ float g_lsum[64 * 4 * L];
__device__ float g_latpart[4 * 64 * DH * L];
__device__ float g_kvl[Bsz * 2 * C * L];
__device__ float g_qlhat[C * L];
__device__ __half g_xT [(size_t)Bsz * NPIX * C];       // x transposed fp16
__device__ __half g_xwT[(size_t)Bsz * NPIX * C];       // attn2 out fp16
__device__ __half g_wA[MROWS * KDIM];                  // stacked w_kv_x ; w_q_x
__device__ __half g_wp[C * KDIM];                      // w_proj

// ---------------- helpers ---------------------------------------------------
__device__ __forceinline__ uint32_t smem_u32(const void* p) {
    uint32_t a;
    asm("{ .reg .u64 t; cvta.to.shared.u64 t, %1; cvt.u32.u64 %0, t; }" : "=r"(a) : "l"(p));
    return a;
}

#define LDSM4(r, addr) \
    asm volatile("ldmatrix.sync.aligned.m8n8.x4.shared.b16 {%0,%1,%2,%3}, [%4];" \
                 : "=r"((r)[0]), "=r"((r)[1]), "=r"((r)[2]), "=r"((r)[3]) : "r"(addr))

#define MMA16816(cc, aa, b0, b1) \
    asm volatile("mma.sync.aligned.m16n8k16.row.col.f32.f16.f16.f32 " \
                 "{%0,%1,%2,%3}, {%4,%5,%6,%7}, {%8,%9}, {%0,%1,%2,%3};" \
                 : "+f"((cc)[0]), "+f"((cc)[1]), "+f"((cc)[2]), "+f"((cc)[3]) \
                 : "r"((aa)[0]), "r"((aa)[1]), "r"((aa)[2]), "r"((aa)[3]), \
                   "r"(b0), "r"(b1))

#define CP_ASYNC16(dst, src) \
    asm volatile("cp.async.cg.shared.global [%0], [%1], 16;" :: "r"(dst), "l"(src))
#define CP_COMMIT() asm volatile("cp.async.commit_group;" ::: "memory")
#define CP_WAIT(n)  asm volatile("cp.async.wait_group %0;" :: "n"(n) : "memory")

// ---------------------------------------------------------------------------
// Fused weight convert for wA: w_kv_x (1024x512) ; w_q_x (512x512) -> fp16
// ---------------------------------------------------------------------------
#define KV4 (2 * C * KDIM / 4)
#define Q4  (C * KDIM / 4)
__global__ __launch_bounds__(256) void wconvA_kernel(
    const float* __restrict__ wkv, const float* __restrict__ wq,
    __half* __restrict__ wA)
{
    int i = blockIdx.x * 256 + threadIdx.x;
    if (i >= KV4 + Q4) return;
    const float* src = (i < KV4) ? (wkv + i * 4) : (wq + (i - KV4) * 4);
    float4 v = *(const float4*)src;
    __half2* o = (__half2*)(wA + i * 4);
    o[0] = __floats2half2_rn(v.x, v.y);
    o[1] = __floats2half2_rn(v.z, v.w);
}

__global__ __launch_bounds__(256) void wconv_kernel(
    const float* __restrict__ a, __half* __restrict__ hi, int n4)
{
    int i = blockIdx.x * 256 + threadIdx.x;
    if (i >= n4) return;
    float4 v = ((const float4*)a)[i];
    __half2* o = (__half2*)(hi + i * 4);
    o[0] = __floats2half2_rn(v.x, v.y);
    o[1] = __floats2half2_rn(v.z, v.w);
}

// ---------------------------------------------------------------------------
// Transpose x: [B,C,N] fp32 -> [B,N,C] fp16. 64c x 32n tiles; half2 writes
// (128B-coalesced stores). grid (128, 8, B), block (32,8).
// ---------------------------------------------------------------------------
__global__ __launch_bounds__(256) void tconv_kernel(
    const float* __restrict__ x, __half* __restrict__ xo)
{
    __shared__ float t[64][33];
    int n0 = blockIdx.x * 32, c0 = blockIdx.y * 64, b = blockIdx.z;
    int tx = threadIdx.x, ty = threadIdx.y;
    const float* xb = x + (size_t)b * C * NPIX;
    #pragma unroll
    for (int i = 0; i < 8; i++)
        t[ty + i * 8][tx] = xb[(size_t)(c0 + ty + i * 8) * NPIX + n0 + tx];
    __syncthreads();
    __half* ob = xo + (size_t)b * NPIX * C;
    #pragma unroll
    for (int i = 0; i < 4; i++) {
        int n = ty + i * 8;
        *(__half2*)&ob[(size_t)(n0 + n) * C + c0 + 2 * tx] =
            __floats2half2_rn(t[2 * tx][n], t[2 * tx + 1][n]);
    }
}

// ---------------------------------------------------------------------------
// HMMA GEMM: C[z][m][n] = sum_k A[m][k]*B[z][n][k], single fp16 term.
// Tile 128x128x64, 256 threads (2x4 warps), 3-stage cp.async, 2 CTAs/SM.
// Output: fp16 (Ch) or fp32+bias (Cf); per-z stride = M*NPIX.
// ---------------------------------------------------------------------------
#define STG 32768
__device__ __forceinline__ void gemm_load_stage(
    char* sm, int stg, int ck, int tid,
    const __half* a0, const __half* b0)
{
    char* d = sm + stg * STG;
    #pragma unroll
    for (int i = 0; i < 8; i++) {
        int u = tid + i * 256;
        int r = u >> 10, idx = u & 1023, row = idx >> 3, c = idx & 7;
        const __half* src = ((r == 0) ? a0 : b0) + (size_t)row * KDIM + ck * 64 + c * 8;
        uint32_t dst = smem_u32(d + r * 16384 + row * 128 + (((c ^ (row & 7))) << 4));
        CP_ASYNC16(dst, src);
    }
    CP_COMMIT();
}

__global__ __launch_bounds__(256, 2) void gemm_mma(
    const __half* __restrict__ A, const __half* __restrict__ B,
    __half* __restrict__ Ch, float* __restrict__ Cf,
    const float* __restrict__ bias, int M)
{
    extern __shared__ char sm[];
    int tid = threadIdx.x, lane = tid & 31, wid = tid >> 5;
    int wm = wid >> 2, wn = wid & 3;
    int m0 = blockIdx.y * 128, n0 = blockIdx.x * 128, z = blockIdx.z;

    const __half* a0p = A + (size_t)m0 * KDIM;
    const __half* b0p = B + ((size_t)z * NPIX + n0) * KDIM;

    float acc[4][4][4];
    #pragma unroll
    for (int i = 0; i < 4; i++)
        #pragma unroll
        for (int j = 0; j < 4; j++)
            #pragma unroll
            for (int k = 0; k < 4; k++) acc[i][j][k] = 0.f;

    gemm_load_stage(sm, 0, 0, tid, a0p, b0p);
    gemm_load_stage(sm, 1, 1, tid, a0p, b0p);

    int a_row = wm * 64 + ((lane >> 3) & 1) * 8 + (lane & 7);
    int a_ck  = (lane >> 4);
    int b_row = wn * 32 + (lane >> 4) * 8 + (lane & 7);
    int b_ck  = ((lane >> 3) & 1);
    uint32_t sbase = smem_u32(sm);

    for (int ck = 0; ck < 8; ck++) {
        if (ck + 2 < 8) {
            gemm_load_stage(sm, (ck + 2) % 3, ck + 2, tid, a0p, b0p);
            CP_WAIT(2);
        } else if (ck + 1 < 8) {
            CP_WAIT(1);
        } else {
            CP_WAIT(0);
        }
        __syncthreads();

        uint32_t st = sbase + (ck % 3) * STG;
        #pragma unroll
        for (int kk = 0; kk < 4; kk++) {
            uint32_t af[4][4];
            #pragma unroll
            for (int mf = 0; mf < 4; mf++) {
                int row = a_row + mf * 16;
                int chv = (kk * 2 + a_ck) ^ (row & 7);
                LDSM4(af[mf], st + row * 128 + (chv << 4));
            }
            uint32_t bf[2][4];
            #pragma unroll
            for (int ng = 0; ng < 2; ng++) {
                int row = b_row + ng * 16;
                int chv = (kk * 2 + b_ck) ^ (row & 7);
                LDSM4(bf[ng], st + 16384 + row * 128 + (chv << 4));
            }
            #pragma unroll
            for (int mf = 0; mf < 4; mf++)
                #pragma unroll
                for (int ng = 0; ng < 2; ng++)
                    #pragma unroll
                    for (int nh = 0; nh < 2; nh++)
                        MMA16816(acc[mf][ng * 2 + nh], af[mf],
                                 bf[ng][nh * 2], bf[ng][nh * 2 + 1]);
        }
        __syncthreads();
    }

    size_t obase = (size_t)z * M * NPIX;
    if (Ch) {
        #pragma unroll
        for (int mf = 0; mf < 4; mf++) {
            int m = m0 + wm * 64 + mf * 16 + (lane >> 2);
            #pragma unroll
            for (int nf = 0; nf < 4; nf++) {
                int n = n0 + wn * 32 + nf * 8 + (lane & 3) * 2;
                *(__half2*)&Ch[obase + (size_t)m * NPIX + n] =
                    __floats2half2_rn(acc[mf][nf][0], acc[mf][nf][1]);
                *(__half2*)&Ch[obase + (size_t)(m + 8) * NPIX + n] =
                    __floats2half2_rn(acc[mf][nf][2], acc[mf][nf][3]);
            }
        }
    } else {
        #pragma unroll
        for (int mf = 0; mf < 4; mf++) {
            int m = m0 + wm * 64 + mf * 16 + (lane >> 2);
            float bb0 = bias ? bias[m] : 0.f;
            float bb8 = bias ? bias[m + 8] : 0.f;
            #pragma unroll
            for (int nf = 0; nf < 4; nf++) {
                int n = n0 + wn * 32 + nf * 8 + (lane & 3) * 2;
                *(float2*)&Cf[obase + (size_t)m * NPIX + n] =
                    make_float2(acc[mf][nf][0] + bb0, acc[mf][nf][1] + bb0);
                *(float2*)&Cf[obase + (size_t)(m + 8) * NPIX + n] =
                    make_float2(acc[mf][nf][2] + bb8, acc[mf][nf][3] + bb8);
            }
        }
    }
}

// ---------------------------------------------------------------------------
// qlhat: normalized latent queries (batch-invariant). grid=8, 256 threads.
// ---------------------------------------------------------------------------
__global__ __launch_bounds__(256) void qlhat_kernel(
    const float* __restrict__ w_q_lat, const float* __restrict__ latents,
    float* __restrict__ qlhat)
{
    int h = blockIdx.x;
    __shared__ float slat[C][L];
    __shared__ float stile[DH][L];
    __shared__ float snorm[L];
    int tid = threadIdx.x;
    for (int i = tid; i < C * L; i += 256) slat[i >> 4][i & 15] = latents[i];
    __syncthreads();
    for (int p = tid; p < DH * L; p += 256) {
        int j = p >> 4, l = p & 15;
        const float* wrow = w_q_lat + (size_t)(h * DH + j) * C;
        float acc = 0.f;
        for (int c2 = 0; c2 < C; c2++) acc += wrow[c2] * slat[c2][l];
        stile[j][l] = acc;
    }
    __syncthreads();
    if (tid < L) {
        float s = 0.f;
        for (int j = 0; j < DH; j++) { float v = stile[j][tid]; s += v * v; }
        snorm[tid] = 1.f / fmaxf(sqrtf(s), EPSN);
    }
    __syncthreads();
    for (int p = tid; p < DH * L; p += 256)
        qlhat[(h * DH + (p >> 4)) * L + (p & 15)] = stile[p >> 4][p & 15] * snorm[p & 15];
}

// ---------------------------------------------------------------------------
// attn1 fused: per (bh, split of 1024 px): exp(logits) -> smem tile [16][1024],
// per-split L-sums -> lsum_g, unnormalized partial P@V -> latpart.
// grid (64, 4), 512 threads, ~69KB dynamic smem.
// ---------------------------------------------------------------------------
__global__ __launch_bounds__(512) void attn1_fused_kernel(
    const __half* __restrict__ kvq, const float* __restrict__ qlhat,
    float* __restrict__ latpart, float* __restrict__ lsum_g)
{
    extern __shared__ float dyn[];
    float* p_sm = dyn;                       // [16][1024] = 64KB
    float (*sql)[L] = (float(*)[L])(dyn + L * 1024);
    float (*wred)[L] = (float(*)[L])(dyn + L * 1024 + DH * L);

    int bh = blockIdx.x, split = blockIdx.y, b = bh >> 3, h = bh & 7;
    const __half* kbase = kvq + ((size_t)b * MROWS + h * DH) * NPIX + split * 1024;
    const __half* vbase = kvq + ((size_t)b * MROWS + 512 + h * DH) * NPIX + split * 1024;
    int tid = threadIdx.x, lane = tid & 31, wrp = tid >> 5;

    for (int i = tid; i < DH * L; i += 512)
        sql[i >> 4][i & 15] = qlhat[(h * DH + (i >> 4)) * L + (i & 15)];
    __syncthreads();

    {
        float dot[2][L], nrm[2] = {0.f, 0.f};
        #pragma unroll
        for (int i = 0; i < 2; i++)
            #pragma unroll
            for (int l = 0; l < L; l++) dot[i][l] = 0.f;
        for (int j = 0; j < DH; j++) {
            __half2 a01 = *(const __half2*)(kbase + (size_t)j * NPIX + 2 * tid);
            float k0 = __low2float(a01), k1 = __high2float(a01);
            nrm[0] += k0 * k0; nrm[1] += k1 * k1;
            #pragma unroll
            for (int l = 0; l < L; l++) {
                float s = sql[j][l];
                dot[0][l] += k0 * s;
                dot[1][l] += k1 * s;
            }
        }
        float inv0 = SCALE / fmaxf(sqrtf(nrm[0]), EPSN);
        float inv1 = SCALE / fmaxf(sqrtf(nrm[1]), EPSN);
        float lsum[L];
        #pragma unroll
        for (int l = 0; l < L; l++) {
            float p0 = __expf(dot[0][l] * inv0);
            float p1 = __expf(dot[1][l] * inv1);
            lsum[l] = p0 + p1;
            *(float2*)&p_sm[l * 1024 + 2 * tid] = make_float2(p0, p1);
        }
        #pragma unroll
        for (int l = 0; l < L; l++) {
            float v = lsum[l];
            #pragma unroll
            for (int o = 16; o; o >>= 1) v += __shfl_xor_sync(0xffffffffu, v, o);
            if (lane == 0) wred[wrp][l] = v;
        }
    }
    __syncthreads();
    if (tid < L) {
        float s = 0.f;
        #pragma unroll
        for (int w = 0; w < 16; w++) s += wred[w][tid];
        lsum_g[bh * 64 + split * 16 + tid] = s;
    }

    float acc[4][L];
    #pragma unroll
    for (int jj = 0; jj < 4; jj++)
        #pragma unroll
        for (int l = 0; l < L; l++) acc[jj][l] = 0.f;

    for (int it = 0; it < 16; it++) {
        int n2 = it * 64 + lane * 2;
        float2 pv[L];
        #pragma unroll
        for (int l = 0; l < L; l++) pv[l] = *(const float2*)&p_sm[l * 1024 + n2];
        #pragma unroll
        for (int jj = 0; jj < 4; jj++) {
            __half2 v2 = *(const __half2*)&vbase[(size_t)(wrp * 4 + jj) * NPIX + n2];
            float v0 = __low2float(v2), v1 = __high2float(v2);
            #pragma unroll
            for (int l = 0; l < L; l++) acc[jj][l] += v0 * pv[l].x + v1 * pv[l].y;
        }
    }
    #pragma unroll
    for (int jj = 0; jj < 4; jj++)
        #pragma unroll
        for (int l = 0; l < L; l++) {
            float v = acc[jj][l];
            #pragma unroll
            for (int o = 16; o; o >>= 1) v += __shfl_xor_sync(0xffffffffu, v, o);
            if (lane == 0)
                latpart[split * 65536 + bh * 1024 + (wrp * 4 + jj) * 16 + l] = v;
        }
}

// ---------------------------------------------------------------------------
// kvl (attn1d fused): reconstruct latread[b] from latpart/lsum inline, then
// kvl[b] = w_kv_lat @ latread; normalize k-part. grid (8, 16), 256 threads.
// ---------------------------------------------------------------------------
__global__ __launch_bounds__(256) void kvl_kernel(
    const float* __restrict__ w_kv_lat, const float* __restrict__ latpart,
    const float* __restrict__ lsum_g, float* __restrict__ kvl)
{
    int b = blockIdx.x, c0 = blockIdx.y * 64;
    __shared__ float slat[C][L];
    __shared__ float stile[64][L];
    __shared__ float snorm[L];
    int tid = threadIdx.x;
    for (int i = tid; i < C * L; i += 256) {
        int c = i >> 4, l = i & 15;
        int h = c >> 6, r = c & 63;
        int bh = b * 8 + h;
        int e = bh * 1024 + r * 16 + l;
        float s = latpart[e] + latpart[65536 + e] + latpart[131072 + e] + latpart[196608 + e];
        float d = lsum_g[bh * 64 + l] + lsum_g[bh * 64 + 16 + l] +
                  lsum_g[bh * 64 + 32 + l] + lsum_g[bh * 64 + 48 + l];
        slat[c][l] = s / d;
    }
    __syncthreads();
    for (int p = tid; p < 64 * L; p += 256) {
        int j = p >> 4, l = p & 15;
        const float* wrow = w_kv_lat + (size_t)(c0 + j) * C;
        float acc = 0.f;
        for (int c2 = 0; c2 < C; c2++) acc += wrow[c2] * slat[c2][l];
        stile[j][l] = acc;
    }
    __syncthreads();
    if (c0 < C) {
        if (tid < L) {
            float s = 0.f;
            for (int j = 0; j < 64; j++) { float v = stile[j][tid]; s += v * v; }
            snorm[tid] = 1.f / fmaxf(sqrtf(s), EPSN);
        }
        __syncthreads();
        for (int p = tid; p < 64 * L; p += 256)
            kvl[((size_t)b * 2 * C + c0 + (p >> 4)) * L + (p & 15)] =
                stile[p >> 4][p & 15] * snorm[p & 15];
    } else {
        for (int p = tid; p < 64 * L; p += 256)
            kvl[((size_t)b * 2 * C + c0 + (p >> 4)) * L + (p & 15)] = stile[p >> 4][p & 15];
    }
}

// ---------------------------------------------------------------------------
// attn2: 2 pixels/thread via half2 q loads; fp16 xwT out.
// grid (16, HEADS, Bsz), 128 threads.
// ---------------------------------------------------------------------------
__global__ __launch_bounds__(128) void attn2_kernel(
    const __half* __restrict__ kvq, const float* __restrict__ kvl,
    __half* __restrict__ xwT)
{
    int b = blockIdx.z, h = blockIdx.y;
    int tid = threadIdx.x;
    int n = blockIdx.x * 256 + 2 * tid;
    __shared__ float skl[DH][L];
    __shared__ float svl[DH][L];
    __shared__ unsigned short sh[DH][256];

    const float* kvlb = kvl + (size_t)b * 2 * C * L;
    for (int i = tid; i < DH * L; i += 128) {
        skl[i >> 4][i & 15] = kvlb[(h * DH + (i >> 4)) * L + (i & 15)];
        svl[i >> 4][i & 15] = kvlb[(C + h * DH + (i >> 4)) * L + (i & 15)];
    }
    __syncthreads();

    const __half* qcol = kvq + ((size_t)b * MROWS + 1024 + h * DH) * NPIX + n;
    float dot[2][L], nrm[2] = {0.f, 0.f};
    #pragma unroll
    for (int i = 0; i < 2; i++)
        #pragma unroll
        for (int l = 0; l < L; l++) dot[i][l] = 0.f;
    for (int j = 0; j < DH; j++) {
        __half2 q2 = *(const __half2*)(qcol + (size_t)j * NPIX);
        float q0 = __low2float(q2), q1 = __high2float(q2);
        nrm[0] += q0 * q0; nrm[1] += q1 * q1;
        #pragma unroll
        for (int l = 0; l < L; l++) {
            float s = skl[j][l];
            dot[0][l] += q0 * s;
            dot[1][l] += q1 * s;
        }
    }
    float is[2];
    #pragma unroll
    for (int i = 0; i < 2; i++) {
        float inv = SCALE / fmaxf(sqrtf(nrm[i]), EPSN);
        float s = 0.f;
        #pragma unroll
        for (int l = 0; l < L; l++) { dot[i][l] = __expf(dot[i][l] * inv); s += dot[i][l]; }
        is[i] = 1.f / s;
    }

    for (int j = 0; j < DH; j++) {
        float a0 = 0.f, a1 = 0.f;
        #pragma unroll
        for (int l = 0; l < L; l++) {
            float v = svl[j][l];
            a0 += dot[0][l] * v;
            a1 += dot[1][l] * v;
        }
        sh[j][2 * tid]     = __half_as_ushort(__float2half_rn(a0 * is[0]));
        sh[j][2 * tid + 1] = __half_as_ushort(__float2half_rn(a1 * is[1]));
    }
    __syncthreads();

    #pragma unroll
    for (int px = 0; px < 2; px++) {
        int pp = 2 * tid + px;
        int np = blockIdx.x * 256 + pp;
        size_t base = ((size_t)b * NPIX + np) * C + h * DH;
        #pragma unroll
        for (int c4 = 0; c4 < 8; c4++) {
            uint32_t wv[4];
            #pragma unroll
            for (int k = 0; k < 4; k++) {
                int j = c4 * 8 + k * 2;
                wv[k] = (uint32_t)sh[j][pp] | ((uint32_t)sh[j + 1][pp] << 16);
            }
            *(uint4*)(xwT + base + c4 * 8) = make_uint4(wv[0], wv[1], wv[2], wv[3]);
        }
    }
}

// ---------------------------------------------------------------------------
// Launch: R8 topology (proven). One side stream for wp conv + qlhat; all
// tensor work and the attention chain serialized on the main stream.
// ---------------------------------------------------------------------------
extern "C" void kernel_launch(void* const* d_in, const int* in_sizes, int n_in,
                              void* d_out, int out_size)
{
    const float* x        = (const float*)d_in[0];
    const float* latents  = (const float*)d_in[1];
    const float* w_q_lat  = (const float*)d_in[2];
    const float* w_kv_x   = (const float*)d_in[3];
    const float* w_q_x    = (const float*)d_in[4];
    const float* w_kv_lat = (const float*)d_in[5];
    const float* w_proj   = (const float*)d_in[6];
    const float* b_proj   = (const float*)d_in[7];
    float* out = (float*)d_out;

    float *lsum, *latpart, *kvl, *qlhat;
    __half *kvq, *xT, *xwT, *wA, *wp;
    cudaGetSymbolAddress((void**)&kvq, g_kvq);
    cudaGetSymbolAddress((void**)&lsum, g_lsum);
    cudaGetSymbolAddress((void**)&latpart, g_latpart);
    cudaGetSymbolAddress((void**)&kvl, g_kvl);
    cudaGetSymbolAddress((void**)&qlhat, g_qlhat);
    cudaGetSymbolAddress((void**)&xT, g_xT);
    cudaGetSymbolAddress((void**)&xwT, g_xwT);
    cudaGetSymbolAddress((void**)&wA, g_wA);
    cudaGetSymbolAddress((void**)&wp, g_wp);

    static cudaStream_t s1 = nullptr;
    static cudaEvent_t evFork = nullptr, evSide = nullptr;
    if (!s1) {
        cudaStreamCreateWithFlags(&s1, cudaStreamNonBlocking);
        cudaEventCreateWithFlags(&evFork, cudaEventDisableTiming);
        cudaEventCreateWithFlags(&evSide, cudaEventDisableTiming);
    }

    cudaFuncSetAttribute(gemm_mma, cudaFuncAttributeMaxDynamicSharedMemorySize, 3 * STG);
    int attn1_smem = (L * 1024 + DH * L + 16 * L) * sizeof(float);
    cudaFuncSetAttribute(attn1_fused_kernel, cudaFuncAttributeMaxDynamicSharedMemorySize, attn1_smem);

    // side stream: proj weight conversion + qlhat (consumed later)
    cudaEventRecord(evFork, 0);
    cudaStreamWaitEvent(s1, evFork, 0);
    wconv_kernel<<<(Q4 + 255) / 256, 256, 0, s1>>>(w_proj, wp, Q4);
    qlhat_kernel<<<HEADS, 256, 0, s1>>>(w_q_lat, latents, qlhat);
    cudaEventRecord(evSide, s1);

    // main chain
    wconvA_kernel<<<(KV4 + Q4 + 255) / 256, 256>>>(w_kv_x, w_q_x, wA);
    tconv_kernel<<<dim3(NPIX / 32, C / 64, Bsz), dim3(32, 8)>>>(x, xT);

    // fused kv+q GEMM (M=1536) -> fp16 kvq
    gemm_mma<<<dim3(32, 12, Bsz), 256, 3 * STG>>>(wA, xT, kvq, nullptr, nullptr, MROWS);

    // join side stream (qlhat needed by attn1, wp by final gemm)
    cudaStreamWaitEvent(0, evSide, 0);

    // latent read attention (fused exp + partial P@V), then fused kvl
    attn1_fused_kernel<<<dim3(64, 4), 512, attn1_smem>>>(kvq, qlhat, latpart, lsum);
    kvl_kernel<<<dim3(Bsz, 16), 256>>>(w_kv_lat, latpart, lsum, kvl);

    // latent write attention -> fp16 xwT
    attn2_kernel<<<dim3(16, HEADS, Bsz), 128>>>(kvq, kvl, xwT);

    // output projection + bias (fp32 out)
    gemm_mma<<<dim3(32, 4, Bsz), 256, 3 * STG>>>(wp, xwT, nullptr, out, b_proj, C);
}

// round 15
// speedup vs baseline: 1.4530x; 1.0216x over previous
#include <cuda_runtime.h>
#include <cuda_fp16.h>
#include <math.h>
#include <stdint.h>

// ---------------------------------------------------------------------------
// LatentMixer on GB300 (sm_103 plain target): single-term fp16 HMMA GEMMs,
// fused attention. R8 stream topology + coalesced tconv + fused wconvA.
// B=8, C=512, N=4096, heads=8, d=64, L=16, scale=0.125
// ---------------------------------------------------------------------------

#define Bsz 8
#define C   512
#define NPIX 4096
#define L   16
#define HEADS 8
#define DH  64
#define SCALE 0.125f
#define EPSN 1e-12f
#define KDIM 512
#define MROWS 1536   // stacked k(512) v(512) q(512)

// ---------------- scratch (device globals; allocation-free contract) -------
__device__ __half g_kvq[(size_t)Bsz * MROWS * NPIX];   // fp16 k/v/q
__device__ float g_lsum[64 * 4 * L];
__device__ float g_latpart[4 * 64 * DH * L];
__device__ float g_latread[Bsz * C * L];
__device__ float g_kvl[Bsz * 2 * C * L];
__device__ float g_qlhat[C * L];
__device__ __half g_xT [(size_t)Bsz * NPIX * C];       // x transposed fp16
__device__ __half g_xwT[(size_t)Bsz * NPIX * C];       // attn2 out fp16
__device__ __half g_wA[MROWS * KDIM];                  // stacked w_kv_x ; w_q_x
__device__ __half g_wp[C * KDIM];                      // w_proj

// ---------------- helpers ---------------------------------------------------
__device__ __forceinline__ uint32_t smem_u32(const void* p) {
    uint32_t a;
    asm("{ .reg .u64 t; cvta.to.shared.u64 t, %1; cvt.u32.u64 %0, t; }" : "=r"(a) : "l"(p));
    return a;
}

#define LDSM4(r, addr) \
    asm volatile("ldmatrix.sync.aligned.m8n8.x4.shared.b16 {%0,%1,%2,%3}, [%4];" \
                 : "=r"((r)[0]), "=r"((r)[1]), "=r"((r)[2]), "=r"((r)[3]) : "r"(addr))

#define MMA16816(cc, aa, b0, b1) \
    asm volatile("mma.sync.aligned.m16n8k16.row.col.f32.f16.f16.f32 " \
                 "{%0,%1,%2,%3}, {%4,%5,%6,%7}, {%8,%9}, {%0,%1,%2,%3};" \
                 : "+f"((cc)[0]), "+f"((cc)[1]), "+f"((cc)[2]), "+f"((cc)[3]) \
                 : "r"((aa)[0]), "r"((aa)[1]), "r"((aa)[2]), "r"((aa)[3]), \
                   "r"(b0), "r"(b1))

#define CP_ASYNC16(dst, src) \
    asm volatile("cp.async.cg.shared.global [%0], [%1], 16;" :: "r"(dst), "l"(src))
#define CP_COMMIT() asm volatile("cp.async.commit_group;" ::: "memory")
#define CP_WAIT(n)  asm volatile("cp.async.wait_group %0;" :: "n"(n) : "memory")

// ---------------------------------------------------------------------------
// Fused weight convert for wA: w_kv_x (1024x512) ; w_q_x (512x512) -> fp16
// ---------------------------------------------------------------------------
#define KV4 (2 * C * KDIM / 4)
#define Q4  (C * KDIM / 4)
__global__ __launch_bounds__(256) void wconvA_kernel(
    const float* __restrict__ wkv, const float* __restrict__ wq,
    __half* __restrict__ wA)
{
    int i = blockIdx.x * 256 + threadIdx.x;
    if (i >= KV4 + Q4) return;
    const float* src = (i < KV4) ? (wkv + i * 4) : (wq + (i - KV4) * 4);
    float4 v = *(const float4*)src;
    __half2* o = (__half2*)(wA + i * 4);
    o[0] = __floats2half2_rn(v.x, v.y);
    o[1] = __floats2half2_rn(v.z, v.w);
}

__global__ __launch_bounds__(256) void wconv_kernel(
    const float* __restrict__ a, __half* __restrict__ hi, int n4)
{
    int i = blockIdx.x * 256 + threadIdx.x;
    if (i >= n4) return;
    float4 v = ((const float4*)a)[i];
    __half2* o = (__half2*)(hi + i * 4);
    o[0] = __floats2half2_rn(v.x, v.y);
    o[1] = __floats2half2_rn(v.z, v.w);
}

// ---------------------------------------------------------------------------
// Transpose x: [B,C,N] fp32 -> [B,N,C] fp16. 64c x 32n tiles; half2 writes
// (128B-coalesced stores). grid (128, 8, B), block (32,8).
// ---------------------------------------------------------------------------
__global__ __launch_bounds__(256) void tconv_kernel(
    const float* __restrict__ x, __half* __restrict__ xo)
{
    __shared__ float t[64][33];
    int n0 = blockIdx.x * 32, c0 = blockIdx.y * 64, b = blockIdx.z;
    int tx = threadIdx.x, ty = threadIdx.y;
    const float* xb = x + (size_t)b * C * NPIX;
    #pragma unroll
    for (int i = 0; i < 8; i++)
        t[ty + i * 8][tx] = xb[(size_t)(c0 + ty + i * 8) * NPIX + n0 + tx];
    __syncthreads();
    __half* ob = xo + (size_t)b * NPIX * C;
    #pragma unroll
    for (int i = 0; i < 4; i++) {
        int n = ty + i * 8;
        *(__half2*)&ob[(size_t)(n0 + n) * C + c0 + 2 * tx] =
            __floats2half2_rn(t[2 * tx][n], t[2 * tx + 1][n]);
    }
}

// ---------------------------------------------------------------------------
// HMMA GEMM: C[z][m][n] = sum_k A[m][k]*B[z][n][k], single fp16 term.
// Tile 128x128x64, 256 threads (2x4 warps), 3-stage cp.async, 2 CTAs/SM.
// Output: fp16 (Ch) or fp32+bias (Cf); per-z stride = M*NPIX.
// ---------------------------------------------------------------------------
#define STG 32768
__device__ __forceinline__ void gemm_load_stage(
    char* sm, int stg, int ck, int tid,
    const __half* a0, const __half* b0)
{
    char* d = sm + stg * STG;
    #pragma unroll
    for (int i = 0; i < 8; i++) {
        int u = tid + i * 256;
        int r = u >> 10, idx = u & 1023, row = idx >> 3, c = idx & 7;
        const __half* src = ((r == 0) ? a0 : b0) + (size_t)row * KDIM + ck * 64 + c * 8;
        uint32_t dst = smem_u32(d + r * 16384 + row * 128 + (((c ^ (row & 7))) << 4));
        CP_ASYNC16(dst, src);
    }
    CP_COMMIT();
}

__global__ __launch_bounds__(256, 2) void gemm_mma(
    const __half* __restrict__ A, const __half* __restrict__ B,
    __half* __restrict__ Ch, float* __restrict__ Cf,
    const float* __restrict__ bias, int M)
{
    extern __shared__ char sm[];
    int tid = threadIdx.x, lane = tid & 31, wid = tid >> 5;
    int wm = wid >> 2, wn = wid & 3;
    int m0 = blockIdx.y * 128, n0 = blockIdx.x * 128, z = blockIdx.z;

    const __half* a0p = A + (size_t)m0 * KDIM;
    const __half* b0p = B + ((size_t)z * NPIX + n0) * KDIM;

    float acc[4][4][4];
    #pragma unroll
    for (int i = 0; i < 4; i++)
        #pragma unroll
        for (int j = 0; j < 4; j++)
            #pragma unroll
            for (int k = 0; k < 4; k++) acc[i][j][k] = 0.f;

    gemm_load_stage(sm, 0, 0, tid, a0p, b0p);
    gemm_load_stage(sm, 1, 1, tid, a0p, b0p);

    int a_row = wm * 64 + ((lane >> 3) & 1) * 8 + (lane & 7);
    int a_ck  = (lane >> 4);
    int b_row = wn * 32 + (lane >> 4) * 8 + (lane & 7);
    int b_ck  = ((lane >> 3) & 1);
    uint32_t sbase = smem_u32(sm);

    for (int ck = 0; ck < 8; ck++) {
        if (ck + 2 < 8) {
            gemm_load_stage(sm, (ck + 2) % 3, ck + 2, tid, a0p, b0p);
            CP_WAIT(2);
        } else if (ck + 1 < 8) {
            CP_WAIT(1);
        } else {
            CP_WAIT(0);
        }
        __syncthreads();

        uint32_t st = sbase + (ck % 3) * STG;
        #pragma unroll
        for (int kk = 0; kk < 4; kk++) {
            uint32_t af[4][4];
            #pragma unroll
            for (int mf = 0; mf < 4; mf++) {
                int row = a_row + mf * 16;
                int chv = (kk * 2 + a_ck) ^ (row & 7);
                LDSM4(af[mf], st + row * 128 + (chv << 4));
            }
            uint32_t bf[2][4];
            #pragma unroll
            for (int ng = 0; ng < 2; ng++) {
                int row = b_row + ng * 16;
                int chv = (kk * 2 + b_ck) ^ (row & 7);
                LDSM4(bf[ng], st + 16384 + row * 128 + (chv << 4));
            }
            #pragma unroll
            for (int mf = 0; mf < 4; mf++)
                #pragma unroll
                for (int ng = 0; ng < 2; ng++)
                    #pragma unroll
                    for (int nh = 0; nh < 2; nh++)
                        MMA16816(acc[mf][ng * 2 + nh], af[mf],
                                 bf[ng][nh * 2], bf[ng][nh * 2 + 1]);
        }
        __syncthreads();
    }

    size_t obase = (size_t)z * M * NPIX;
    if (Ch) {
        #pragma unroll
        for (int mf = 0; mf < 4; mf++) {
            int m = m0 + wm * 64 + mf * 16 + (lane >> 2);
            #pragma unroll
            for (int nf = 0; nf < 4; nf++) {
                int n = n0 + wn * 32 + nf * 8 + (lane & 3) * 2;
                *(__half2*)&Ch[obase + (size_t)m * NPIX + n] =
                    __floats2half2_rn(acc[mf][nf][0], acc[mf][nf][1]);
                *(__half2*)&Ch[obase + (size_t)(m + 8) * NPIX + n] =
                    __floats2half2_rn(acc[mf][nf][2], acc[mf][nf][3]);
            }
        }
    } else {
        #pragma unroll
        for (int mf = 0; mf < 4; mf++) {
            int m = m0 + wm * 64 + mf * 16 + (lane >> 2);
            float bb0 = bias ? bias[m] : 0.f;
            float bb8 = bias ? bias[m + 8] : 0.f;
            #pragma unroll
            for (int nf = 0; nf < 4; nf++) {
                int n = n0 + wn * 32 + nf * 8 + (lane & 3) * 2;
                *(float2*)&Cf[obase + (size_t)m * NPIX + n] =
                    make_float2(acc[mf][nf][0] + bb0, acc[mf][nf][1] + bb0);
                *(float2*)&Cf[obase + (size_t)(m + 8) * NPIX + n] =
                    make_float2(acc[mf][nf][2] + bb8, acc[mf][nf][3] + bb8);
            }
        }
    }
}

// ---------------------------------------------------------------------------
// qlhat: normalized latent queries (batch-invariant). grid=8, 256 threads.
// ---------------------------------------------------------------------------
__global__ __launch_bounds__(256) void qlhat_kernel(
    const float* __restrict__ w_q_lat, const float* __restrict__ latents,
    float* __restrict__ qlhat)
{
    int h = blockIdx.x;
    __shared__ float slat[C][L];
    __shared__ float stile[DH][L];
    __shared__ float snorm[L];
    int tid = threadIdx.x;
    for (int i = tid; i < C * L; i += 256) slat[i >> 4][i & 15] = latents[i];
    __syncthreads();
    for (int p = tid; p < DH * L; p += 256) {
        int j = p >> 4, l = p & 15;
        const float* wrow = w_q_lat + (size_t)(h * DH + j) * C;
        float acc = 0.f;
        for (int c2 = 0; c2 < C; c2++) acc += wrow[c2] * slat[c2][l];
        stile[j][l] = acc;
    }
    __syncthreads();
    if (tid < L) {
        float s = 0.f;
        for (int j = 0; j < DH; j++) { float v = stile[j][tid]; s += v * v; }
        snorm[tid] = 1.f / fmaxf(sqrtf(s), EPSN);
    }
    __syncthreads();
    for (int p = tid; p < DH * L; p += 256)
        qlhat[(h * DH + (p >> 4)) * L + (p & 15)] = stile[p >> 4][p & 15] * snorm[p & 15];
}

// ---------------------------------------------------------------------------
// attn1 fused: per (bh, split of 1024 px): exp(logits) -> smem tile [16][1024],
// per-split L-sums -> lsum_g, unnormalized partial P@V -> latpart.
// grid (64, 4), 512 threads, ~69KB dynamic smem.
// ---------------------------------------------------------------------------
__global__ __launch_bounds__(512) void attn1_fused_kernel(
    const __half* __restrict__ kvq, const float* __restrict__ qlhat,
    float* __restrict__ latpart, float* __restrict__ lsum_g)
{
    extern __shared__ float dyn[];
    float* p_sm = dyn;                       // [16][1024] = 64KB
    float (*sql)[L] = (float(*)[L])(dyn + L * 1024);
    float (*wred)[L] = (float(*)[L])(dyn + L * 1024 + DH * L);

    int bh = blockIdx.x, split = blockIdx.y, b = bh >> 3, h = bh & 7;
    const __half* kbase = kvq + ((size_t)b * MROWS + h * DH) * NPIX + split * 1024;
    const __half* vbase = kvq + ((size_t)b * MROWS + 512 + h * DH) * NPIX + split * 1024;
    int tid = threadIdx.x, lane = tid & 31, wrp = tid >> 5;

    for (int i = tid; i < DH * L; i += 512)
        sql[i >> 4][i & 15] = qlhat[(h * DH + (i >> 4)) * L + (i & 15)];
    __syncthreads();

    {
        float dot[2][L], nrm[2] = {0.f, 0.f};
        #pragma unroll
        for (int i = 0; i < 2; i++)
            #pragma unroll
            for (int l = 0; l < L; l++) dot[i][l] = 0.f;
        for (int j = 0; j < DH; j++) {
            __half2 a01 = *(const __half2*)(kbase + (size_t)j * NPIX + 2 * tid);
            float k0 = __low2float(a01), k1 = __high2float(a01);
            nrm[0] += k0 * k0; nrm[1] += k1 * k1;
            #pragma unroll
            for (int l = 0; l < L; l++) {
                float s = sql[j][l];
                dot[0][l] += k0 * s;
                dot[1][l] += k1 * s;
            }
        }
        float inv0 = SCALE / fmaxf(sqrtf(nrm[0]), EPSN);
        float inv1 = SCALE / fmaxf(sqrtf(nrm[1]), EPSN);
        float lsum[L];
        #pragma unroll
        for (int l = 0; l < L; l++) {
            float p0 = __expf(dot[0][l] * inv0);
            float p1 = __expf(dot[1][l] * inv1);
            lsum[l] = p0 + p1;
            *(float2*)&p_sm[l * 1024 + 2 * tid] = make_float2(p0, p1);
        }
        #pragma unroll
        for (int l = 0; l < L; l++) {
            float v = lsum[l];
            #pragma unroll
            for (int o = 16; o; o >>= 1) v += __shfl_xor_sync(0xffffffffu, v, o);
            if (lane == 0) wred[wrp][l] = v;
        }
    }
    __syncthreads();
    if (tid < L) {
        float s = 0.f;
        #pragma unroll
        for (int w = 0; w < 16; w++) s += wred[w][tid];
        lsum_g[bh * 64 + split * 16 + tid] = s;
    }

    float acc[4][L];
    #pragma unroll
    for (int jj = 0; jj < 4; jj++)
        #pragma unroll
        for (int l = 0; l < L; l++) acc[jj][l] = 0.f;

    for (int it = 0; it < 16; it++) {
        int n2 = it * 64 + lane * 2;
        float2 pv[L];
        #pragma unroll
        for (int l = 0; l < L; l++) pv[l] = *(const float2*)&p_sm[l * 1024 + n2];
        #pragma unroll
        for (int jj = 0; jj < 4; jj++) {
            __half2 v2 = *(const __half2*)&vbase[(size_t)(wrp * 4 + jj) * NPIX + n2];
            float v0 = __low2float(v2), v1 = __high2float(v2);
            #pragma unroll
            for (int l = 0; l < L; l++) acc[jj][l] += v0 * pv[l].x + v1 * pv[l].y;
        }
    }
    #pragma unroll
    for (int jj = 0; jj < 4; jj++)
        #pragma unroll
        for (int l = 0; l < L; l++) {
            float v = acc[jj][l];
            #pragma unroll
            for (int o = 16; o; o >>= 1) v += __shfl_xor_sync(0xffffffffu, v, o);
            if (lane == 0)
                latpart[split * 65536 + bh * 1024 + (wrp * 4 + jj) * 16 + l] = v;
        }
}

// attn1d: reduce splits, compute sinv inline, scale -> latread. grid 256x256.
__global__ __launch_bounds__(256) void attn1d_kernel(
    const float* __restrict__ latpart, const float* __restrict__ lsum_g,
    float* __restrict__ latread)
{
    int e = blockIdx.x * 256 + threadIdx.x;
    int bh = e >> 10, rem = e & 1023, r = rem >> 4, l = rem & 15;
    float s = latpart[e] + latpart[65536 + e] + latpart[131072 + e] + latpart[196608 + e];
    float d = lsum_g[bh * 64 + l] + lsum_g[bh * 64 + 16 + l] +
              lsum_g[bh * 64 + 32 + l] + lsum_g[bh * 64 + 48 + l];
    int b = bh >> 3, h = bh & 7;
    latread[((size_t)b * C + h * DH + r) * L + l] = s / d;
}

// ---------------------------------------------------------------------------
// kvl: kvl[b] = w_kv_lat @ lat_read[b]; normalize k-part per (head,l).
// ---------------------------------------------------------------------------
__global__ __launch_bounds__(256) void kvl_kernel(
    const float* __restrict__ w_kv_lat, const float* __restrict__ latread,
    float* __restrict__ kvl)
{
    int b = blockIdx.x, c0 = blockIdx.y * 64;
    __shared__ float slat[C][L];
    __shared__ float stile[64][L];
    __shared__ float snorm[L];
    int tid = threadIdx.x;
    const float* lr = latread + (size_t)b * C * L;
    for (int i = tid; i < C * L; i += 256) slat[i >> 4][i & 15] = lr[i];
    __syncthreads();
    for (int p = tid; p < 64 * L; p += 256) {
        int j = p >> 4, l = p & 15;
        const float* wrow = w_kv_lat + (size_t)(c0 + j) * C;
        float acc = 0.f;
        for (int c2 = 0; c2 < C; c2++) acc += wrow[c2] * slat[c2][l];
        stile[j][l] = acc;
    }
    __syncthreads();
    if (c0 < C) {
        if (tid < L) {
            float s = 0.f;
            for (int j = 0; j < 64; j++) { float v = stile[j][tid]; s += v * v; }
            snorm[tid] = 1.f / fmaxf(sqrtf(s), EPSN);
        }
        __syncthreads();
        for (int p = tid; p < 64 * L; p += 256)
            kvl[((size_t)b * 2 * C + c0 + (p >> 4)) * L + (p & 15)] =
                stile[p >> 4][p & 15] * snorm[p & 15];
    } else {
        for (int p = tid; p < 64 * L; p += 256)
            kvl[((size_t)b * 2 * C + c0 + (p >> 4)) * L + (p & 15)] = stile[p >> 4][p & 15];
    }
}

// ---------------------------------------------------------------------------
// attn2: 2 pixels/thread via half2 q loads; fp16 xwT out.
// grid (16, HEADS, Bsz), 128 threads.
// ---------------------------------------------------------------------------
__global__ __launch_bounds__(128) void attn2_kernel(
    const __half* __restrict__ kvq, const float* __restrict__ kvl,
    __half* __restrict__ xwT)
{
    int b = blockIdx.z, h = blockIdx.y;
    int tid = threadIdx.x;
    int n = blockIdx.x * 256 + 2 * tid;
    __shared__ float skl[DH][L];
    __shared__ float svl[DH][L];
    __shared__ unsigned short sh[DH][256];

    const float* kvlb = kvl + (size_t)b * 2 * C * L;
    for (int i = tid; i < DH * L; i += 128) {
        skl[i >> 4][i & 15] = kvlb[(h * DH + (i >> 4)) * L + (i & 15)];
        svl[i >> 4][i & 15] = kvlb[(C + h * DH + (i >> 4)) * L + (i & 15)];
    }
    __syncthreads();

    const __half* qcol = kvq + ((size_t)b * MROWS + 1024 + h * DH) * NPIX + n;
    float dot[2][L], nrm[2] = {0.f, 0.f};
    #pragma unroll
    for (int i = 0; i < 2; i++)
        #pragma unroll
        for (int l = 0; l < L; l++) dot[i][l] = 0.f;
    for (int j = 0; j < DH; j++) {
        __half2 q2 = *(const __half2*)(qcol + (size_t)j * NPIX);
        float q0 = __low2float(q2), q1 = __high2float(q2);
        nrm[0] += q0 * q0; nrm[1] += q1 * q1;
        #pragma unroll
        for (int l = 0; l < L; l++) {
            float s = skl[j][l];
            dot[0][l] += q0 * s;
            dot[1][l] += q1 * s;
        }
    }
    float is[2];
    #pragma unroll
    for (int i = 0; i < 2; i++) {
        float inv = SCALE / fmaxf(sqrtf(nrm[i]), EPSN);
        float s = 0.f;
        #pragma unroll
        for (int l = 0; l < L; l++) { dot[i][l] = __expf(dot[i][l] * inv); s += dot[i][l]; }
        is[i] = 1.f / s;
    }

    for (int j = 0; j < DH; j++) {
        float a0 = 0.f, a1 = 0.f;
        #pragma unroll
        for (int l = 0; l < L; l++) {
            float v = svl[j][l];
            a0 += dot[0][l] * v;
            a1 += dot[1][l] * v;
        }
        sh[j][2 * tid]     = __half_as_ushort(__float2half_rn(a0 * is[0]));
        sh[j][2 * tid + 1] = __half_as_ushort(__float2half_rn(a1 * is[1]));
    }
    __syncthreads();

    #pragma unroll
    for (int px = 0; px < 2; px++) {
        int pp = 2 * tid + px;
        int np = blockIdx.x * 256 + pp;
        size_t base = ((size_t)b * NPIX + np) * C + h * DH;
        #pragma unroll
        for (int c4 = 0; c4 < 8; c4++) {
            uint32_t wv[4];
            #pragma unroll
            for (int k = 0; k < 4; k++) {
                int j = c4 * 8 + k * 2;
                wv[k] = (uint32_t)sh[j][pp] | ((uint32_t)sh[j + 1][pp] << 16);
            }
            *(uint4*)(xwT + base + c4 * 8) = make_uint4(wv[0], wv[1], wv[2], wv[3]);
        }
    }
}

// ---------------------------------------------------------------------------
// Launch: R8 topology (proven). One side stream for wp conv + qlhat; all
// tensor work and the attention chain serialized on the main stream.
// ---------------------------------------------------------------------------
extern "C" void kernel_launch(void* const* d_in, const int* in_sizes, int n_in,
                              void* d_out, int out_size)
{
    const float* x        = (const float*)d_in[0];
    const float* latents  = (const float*)d_in[1];
    const float* w_q_lat  = (const float*)d_in[2];
    const float* w_kv_x   = (const float*)d_in[3];
    const float* w_q_x    = (const float*)d_in[4];
    const float* w_kv_lat = (const float*)d_in[5];
    const float* w_proj   = (const float*)d_in[6];
    const float* b_proj   = (const float*)d_in[7];
    float* out = (float*)d_out;

    float *lsum, *latpart, *latread, *kvl, *qlhat;
    __half *kvq, *xT, *xwT, *wA, *wp;
    cudaGetSymbolAddress((void**)&kvq, g_kvq);
    cudaGetSymbolAddress((void**)&lsum, g_lsum);
    cudaGetSymbolAddress((void**)&latpart, g_latpart);
    cudaGetSymbolAddress((void**)&latread, g_latread);
    cudaGetSymbolAddress((void**)&kvl, g_kvl);
    cudaGetSymbolAddress((void**)&qlhat, g_qlhat);
    cudaGetSymbolAddress((void**)&xT, g_xT);
    cudaGetSymbolAddress((void**)&xwT, g_xwT);
    cudaGetSymbolAddress((void**)&wA, g_wA);
    cudaGetSymbolAddress((void**)&wp, g_wp);

    static cudaStream_t s1 = nullptr;
    static cudaEvent_t evFork = nullptr, evSide = nullptr;
    if (!s1) {
        cudaStreamCreateWithFlags(&s1, cudaStreamNonBlocking);
        cudaEventCreateWithFlags(&evFork, cudaEventDisableTiming);
        cudaEventCreateWithFlags(&evSide, cudaEventDisableTiming);
    }

    cudaFuncSetAttribute(gemm_mma, cudaFuncAttributeMaxDynamicSharedMemorySize, 3 * STG);
    int attn1_smem = (L * 1024 + DH * L + 16 * L) * sizeof(float);
    cudaFuncSetAttribute(attn1_fused_kernel, cudaFuncAttributeMaxDynamicSharedMemorySize, attn1_smem);

    // side stream: proj weight conversion + qlhat (consumed later)
    cudaEventRecord(evFork, 0);
    cudaStreamWaitEvent(s1, evFork, 0);
    wconv_kernel<<<(Q4 + 255) / 256, 256, 0, s1>>>(w_proj, wp, Q4);
    qlhat_kernel<<<HEADS, 256, 0, s1>>>(w_q_lat, latents, qlhat);
    cudaEventRecord(evSide, s1);

    // main chain
    wconvA_kernel<<<(KV4 + Q4 + 255) / 256, 256>>>(w_kv_x, w_q_x, wA);
    tconv_kernel<<<dim3(NPIX / 32, C / 64, Bsz), dim3(32, 8)>>>(x, xT);

    // fused kv+q GEMM (M=1536) -> fp16 kvq
    gemm_mma<<<dim3(32, 12, Bsz), 256, 3 * STG>>>(wA, xT, kvq, nullptr, nullptr, MROWS);

    // join side stream (qlhat needed by attn1, wp by final gemm)
    cudaStreamWaitEvent(0, evSide, 0);

    // latent read attention (fused exp + partial P@V)
    attn1_fused_kernel<<<dim3(64, 4), 512, attn1_smem>>>(kvq, qlhat, latpart, lsum);
    attn1d_kernel<<<256, 256>>>(latpart, lsum, latread);

    kvl_kernel<<<dim3(Bsz, 16), 256>>>(w_kv_lat, latread, kvl);

    // latent write attention -> fp16 xwT
    attn2_kernel<<<dim3(16, HEADS, Bsz), 128>>>(kvq, kvl, xwT);

    // output projection + bias (fp32 out)
    gemm_mma<<<dim3(32, 4, Bsz), 256, 3 * STG>>>(wp, xwT, nullptr, out, b_proj, C);
}

// round 17
// speedup vs baseline: 1.5141x; 1.0420x over previous
#include <cuda_runtime.h>
#include <cuda_fp16.h>
#include <math.h>
#include <stdint.h>

// ---------------------------------------------------------------------------
// LatentMixer on GB300 (sm_103 plain target): single-term fp16 HMMA GEMMs,
// fused attention. R8 topology + coalesced tconv + 1-sync/chunk GEMM mainloop
// (correct order: wait -> sync -> issue -> compute).
// B=8, C=512, N=4096, heads=8, d=64, L=16, scale=0.125
// ---------------------------------------------------------------------------

#define Bsz 8
#define C   512
#define NPIX 4096
#define L   16
#define HEADS 8
#define DH  64
#define SCALE 0.125f
#define EPSN 1e-12f
#define KDIM 512
#define MROWS 1536   // stacked k(512) v(512) q(512)

// ---------------- scratch (device globals; allocation-free contract) -------
__device__ __half g_kvq[(size_t)Bsz * MROWS * NPIX];   // fp16 k/v/q
__device__ float g_lsum[64 * 4 * L];
__device__ float g_latpart[4 * 64 * DH * L];
__device__ float g_latread[Bsz * C * L];
__device__ float g_kvl[Bsz * 2 * C * L];
__device__ float g_qlhat[C * L];
__device__ __half g_xT [(size_t)Bsz * NPIX * C];       // x transposed fp16
__device__ __half g_xwT[(size_t)Bsz * NPIX * C];       // attn2 out fp16
__device__ __half g_wA[MROWS * KDIM];                  // stacked w_kv_x ; w_q_x
__device__ __half g_wp[C * KDIM];                      // w_proj

// ---------------- helpers ---------------------------------------------------
__device__ __forceinline__ uint32_t smem_u32(const void* p) {
    uint32_t a;
    asm("{ .reg .u64 t; cvta.to.shared.u64 t, %1; cvt.u32.u64 %0, t; }" : "=r"(a) : "l"(p));
    return a;
}

#define LDSM4(r, addr) \
    asm volatile("ldmatrix.sync.aligned.m8n8.x4.shared.b16 {%0,%1,%2,%3}, [%4];" \
                 : "=r"((r)[0]), "=r"((r)[1]), "=r"((r)[2]), "=r"((r)[3]) : "r"(addr))

#define MMA16816(cc, aa, b0, b1) \
    asm volatile("mma.sync.aligned.m16n8k16.row.col.f32.f16.f16.f32 " \
                 "{%0,%1,%2,%3}, {%4,%5,%6,%7}, {%8,%9}, {%0,%1,%2,%3};" \
                 : "+f"((cc)[0]), "+f"((cc)[1]), "+f"((cc)[2]), "+f"((cc)[3]) \
                 : "r"((aa)[0]), "r"((aa)[1]), "r"((aa)[2]), "r"((aa)[3]), \
                   "r"(b0), "r"(b1))

#define CP_ASYNC16(dst, src) \
    asm volatile("cp.async.cg.shared.global [%0], [%1], 16;" :: "r"(dst), "l"(src))
#define CP_COMMIT() asm volatile("cp.async.commit_group;" ::: "memory")
#define CP_WAIT(n)  asm volatile("cp.async.wait_group %0;" :: "n"(n) : "memory")

// ---------------------------------------------------------------------------
// Fused weight convert for wA: w_kv_x (1024x512) ; w_q_x (512x512) -> fp16
// ---------------------------------------------------------------------------
#define KV4 (2 * C * KDIM / 4)
#define Q4  (C * KDIM / 4)
__global__ __launch_bounds__(256) void wconvA_kernel(
    const float* __restrict__ wkv, const float* __restrict__ wq,
    __half* __restrict__ wA)
{
    int i = blockIdx.x * 256 + threadIdx.x;
    if (i >= KV4 + Q4) return;
    const float* src = (i < KV4) ? (wkv + i * 4) : (wq + (i - KV4) * 4);
    float4 v = *(const float4*)src;
    __half2* o = (__half2*)(wA + i * 4);
    o[0] = __floats2half2_rn(v.x, v.y);
    o[1] = __floats2half2_rn(v.z, v.w);
}

__global__ __launch_bounds__(256) void wconv_kernel(
    const float* __restrict__ a, __half* __restrict__ hi, int n4)
{
    int i = blockIdx.x * 256 + threadIdx.x;
    if (i >= n4) return;
    float4 v = ((const float4*)a)[i];
    __half2* o = (__half2*)(hi + i * 4);
    o[0] = __floats2half2_rn(v.x, v.y);
    o[1] = __floats2half2_rn(v.z, v.w);
}

// ---------------------------------------------------------------------------
// Transpose x: [B,C,N] fp32 -> [B,N,C] fp16. 64c x 32n tiles; half2 writes.
// ---------------------------------------------------------------------------
__global__ __launch_bounds__(256) void tconv_kernel(
    const float* __restrict__ x, __half* __restrict__ xo)
{
    __shared__ float t[64][33];
    int n0 = blockIdx.x * 32, c0 = blockIdx.y * 64, b = blockIdx.z;
    int tx = threadIdx.x, ty = threadIdx.y;
    const float* xb = x + (size_t)b * C * NPIX;
    #pragma unroll
    for (int i = 0; i < 8; i++)
        t[ty + i * 8][tx] = xb[(size_t)(c0 + ty + i * 8) * NPIX + n0 + tx];
    __syncthreads();
    __half* ob = xo + (size_t)b * NPIX * C;
    #pragma unroll
    for (int i = 0; i < 4; i++) {
        int n = ty + i * 8;
        *(__half2*)&ob[(size_t)(n0 + n) * C + c0 + 2 * tx] =
            __floats2half2_rn(t[2 * tx][n], t[2 * tx + 1][n]);
    }
}

// ---------------------------------------------------------------------------
// HMMA GEMM: C[z][m][n] = sum_k A[m][k]*B[z][n][k], single fp16 term.
// Tile 128x128x64, 256 threads (2x4 warps), 3-stage cp.async, 2 CTAs/SM.
// One __syncthreads per chunk, placed AFTER cp.async.wait (correct ordering).
// ---------------------------------------------------------------------------
#define STG 32768
__device__ __forceinline__ void gemm_load_stage(
    char* sm, int stg, int ck, int tid,
    const __half* a0, const __half* b0)
{
    char* d = sm + stg * STG;
    #pragma unroll
    for (int i = 0; i < 8; i++) {
        int u = tid + i * 256;
        int r = u >> 10, idx = u & 1023, row = idx >> 3, c = idx & 7;
        const __half* src = ((r == 0) ? a0 : b0) + (size_t)row * KDIM + ck * 64 + c * 8;
        uint32_t dst = smem_u32(d + r * 16384 + row * 128 + (((c ^ (row & 7))) << 4));
        CP_ASYNC16(dst, src);
    }
    CP_COMMIT();
}

__global__ __launch_bounds__(256, 2) void gemm_mma(
    const __half* __restrict__ A, const __half* __restrict__ B,
    __half* __restrict__ Ch, float* __restrict__ Cf,
    const float* __restrict__ bias, int M)
{
    extern __shared__ char sm[];
    int tid = threadIdx.x, lane = tid & 31, wid = tid >> 5;
    int wm = wid >> 2, wn = wid & 3;
    int m0 = blockIdx.y * 128, n0 = blockIdx.x * 128, z = blockIdx.z;

    const __half* a0p = A + (size_t)m0 * KDIM;
    const __half* b0p = B + ((size_t)z * NPIX + n0) * KDIM;

    float acc[4][4][4];
    #pragma unroll
    for (int i = 0; i < 4; i++)
        #pragma unroll
        for (int j = 0; j < 4; j++)
            #pragma unroll
            for (int k = 0; k < 4; k++) acc[i][j][k] = 0.f;

    gemm_load_stage(sm, 0, 0, tid, a0p, b0p);
    gemm_load_stage(sm, 1, 1, tid, a0p, b0p);

    int a_row = wm * 64 + ((lane >> 3) & 1) * 8 + (lane & 7);
    int a_ck  = (lane >> 4);
    int b_row = wn * 32 + (lane >> 4) * 8 + (lane & 7);
    int b_ck  = ((lane >> 3) & 1);
    uint32_t sbase = smem_u32(sm);

    for (int ck = 0; ck < 8; ck++) {
        // group accounting: prologue issued groups 0,1; iter j issues group j+2.
        // Need group ck complete here -> at most 1 newer pending while still
        // issuing (ck<7), else 0.
        if (ck < 7) { CP_WAIT(1); } else { CP_WAIT(0); }
        // barrier AFTER the wait: all threads' stage-ck data visible to all;
        // also proves every warp finished computing chunk ck-1, so stage
        // (ck+2)%3 == (ck-1)%3 is free to overwrite below.
        __syncthreads();
        if (ck + 2 < 8)
            gemm_load_stage(sm, (ck + 2) % 3, ck + 2, tid, a0p, b0p);

        uint32_t st = sbase + (ck % 3) * STG;
        #pragma unroll
        for (int kk = 0; kk < 4; kk++) {
            uint32_t af[4][4];
            #pragma unroll
            for (int mf = 0; mf < 4; mf++) {
                int row = a_row + mf * 16;
                int chv = (kk * 2 + a_ck) ^ (row & 7);
                LDSM4(af[mf], st + row * 128 + (chv << 4));
            }
            uint32_t bf[2][4];
            #pragma unroll
            for (int ng = 0; ng < 2; ng++) {
                int row = b_row + ng * 16;
                int chv = (kk * 2 + b_ck) ^ (row & 7);
                LDSM4(bf[ng], st + 16384 + row * 128 + (chv << 4));
            }
            #pragma unroll
            for (int mf = 0; mf < 4; mf++)
                #pragma unroll
                for (int ng = 0; ng < 2; ng++)
                    #pragma unroll
                    for (int nh = 0; nh < 2; nh++)
                        MMA16816(acc[mf][ng * 2 + nh], af[mf],
                                 bf[ng][nh * 2], bf[ng][nh * 2 + 1]);
        }
    }

    size_t obase = (size_t)z * M * NPIX;
    if (Ch) {
        #pragma unroll
        for (int mf = 0; mf < 4; mf++) {
            int m = m0 + wm * 64 + mf * 16 + (lane >> 2);
            #pragma unroll
            for (int nf = 0; nf < 4; nf++) {
                int n = n0 + wn * 32 + nf * 8 + (lane & 3) * 2;
                *(__half2*)&Ch[obase + (size_t)m * NPIX + n] =
                    __floats2half2_rn(acc[mf][nf][0], acc[mf][nf][1]);
                *(__half2*)&Ch[obase + (size_t)(m + 8) * NPIX + n] =
                    __floats2half2_rn(acc[mf][nf][2], acc[mf][nf][3]);
            }
        }
    } else {
        #pragma unroll
        for (int mf = 0; mf < 4; mf++) {
            int m = m0 + wm * 64 + mf * 16 + (lane >> 2);
            float bb0 = bias ? bias[m] : 0.f;
            float bb8 = bias ? bias[m + 8] : 0.f;
            #pragma unroll
            for (int nf = 0; nf < 4; nf++) {
                int n = n0 + wn * 32 + nf * 8 + (lane & 3) * 2;
                *(float2*)&Cf[obase + (size_t)m * NPIX + n] =
                    make_float2(acc[mf][nf][0] + bb0, acc[mf][nf][1] + bb0);
                *(float2*)&Cf[obase + (size_t)(m + 8) * NPIX + n] =
                    make_float2(acc[mf][nf][2] + bb8, acc[mf][nf][3] + bb8);
            }
        }
    }
}

// ---------------------------------------------------------------------------
// qlhat: normalized latent queries (batch-invariant). grid=8, 256 threads.
// ---------------------------------------------------------------------------
__global__ __launch_bounds__(256) void qlhat_kernel(
    const float* __restrict__ w_q_lat, const float* __restrict__ latents,
    float* __restrict__ qlhat)
{
    int h = blockIdx.x;
    __shared__ float slat[C][L];
    __shared__ float stile[DH][L];
    __shared__ float snorm[L];
    int tid = threadIdx.x;
    for (int i = tid; i < C * L; i += 256) slat[i >> 4][i & 15] = latents[i];
    __syncthreads();
    for (int p = tid; p < DH * L; p += 256) {
        int j = p >> 4, l = p & 15;
        const float* wrow = w_q_lat + (size_t)(h * DH + j) * C;
        float acc = 0.f;
        for (int c2 = 0; c2 < C; c2++) acc += wrow[c2] * slat[c2][l];
        stile[j][l] = acc;
    }
    __syncthreads();
    if (tid < L) {
        float s = 0.f;
        for (int j = 0; j < DH; j++) { float v = stile[j][tid]; s += v * v; }
        snorm[tid] = 1.f / fmaxf(sqrtf(s), EPSN);
    }
    __syncthreads();
    for (int p = tid; p < DH * L; p += 256)
        qlhat[(h * DH + (p >> 4)) * L + (p & 15)] = stile[p >> 4][p & 15] * snorm[p & 15];
}

// ---------------------------------------------------------------------------
// attn1 fused: per (bh, split of 1024 px): exp(logits) -> smem tile [16][1024],
// per-split L-sums -> lsum_g, unnormalized partial P@V -> latpart.
// grid (64, 4), 512 threads, ~69KB dynamic smem.
// ---------------------------------------------------------------------------
__global__ __launch_bounds__(512) void attn1_fused_kernel(
    const __half* __restrict__ kvq, const float* __restrict__ qlhat,
    float* __restrict__ latpart, float* __restrict__ lsum_g)
{
    extern __shared__ float dyn[];
    float* p_sm = dyn;                       // [16][1024] = 64KB
    float (*sql)[L] = (float(*)[L])(dyn + L * 1024);
    float (*wred)[L] = (float(*)[L])(dyn + L * 1024 + DH * L);

    int bh = blockIdx.x, split = blockIdx.y, b = bh >> 3, h = bh & 7;
    const __half* kbase = kvq + ((size_t)b * MROWS + h * DH) * NPIX + split * 1024;
    const __half* vbase = kvq + ((size_t)b * MROWS + 512 + h * DH) * NPIX + split * 1024;
    int tid = threadIdx.x, lane = tid & 31, wrp = tid >> 5;

    for (int i = tid; i < DH * L; i += 512)
        sql[i >> 4][i & 15] = qlhat[(h * DH + (i >> 4)) * L + (i & 15)];
    __syncthreads();

    {
        float dot[2][L], nrm[2] = {0.f, 0.f};
        #pragma unroll
        for (int i = 0; i < 2; i++)
            #pragma unroll
            for (int l = 0; l < L; l++) dot[i][l] = 0.f;
        for (int j = 0; j < DH; j++) {
            __half2 a01 = *(const __half2*)(kbase + (size_t)j * NPIX + 2 * tid);
            float k0 = __low2float(a01), k1 = __high2float(a01);
            nrm[0] += k0 * k0; nrm[1] += k1 * k1;
            #pragma unroll
            for (int l = 0; l < L; l++) {
                float s = sql[j][l];
                dot[0][l] += k0 * s;
                dot[1][l] += k1 * s;
            }
        }
        float inv0 = SCALE / fmaxf(sqrtf(nrm[0]), EPSN);
        float inv1 = SCALE / fmaxf(sqrtf(nrm[1]), EPSN);
        float lsum[L];
        #pragma unroll
        for (int l = 0; l < L; l++) {
            float p0 = __expf(dot[0][l] * inv0);
            float p1 = __expf(dot[1][l] * inv1);
            lsum[l] = p0 + p1;
            *(float2*)&p_sm[l * 1024 + 2 * tid] = make_float2(p0, p1);
        }
        #pragma unroll
        for (int l = 0; l < L; l++) {
            float v = lsum[l];
            #pragma unroll
            for (int o = 16; o; o >>= 1) v += __shfl_xor_sync(0xffffffffu, v, o);
            if (lane == 0) wred[wrp][l] = v;
        }
    }
    __syncthreads();
    if (tid < L) {
        float s = 0.f;
        #pragma unroll
        for (int w = 0; w < 16; w++) s += wred[w][tid];
        lsum_g[bh * 64 + split * 16 + tid] = s;
    }

    float acc[4][L];
    #pragma unroll
    for (int jj = 0; jj < 4; jj++)
        #pragma unroll
        for (int l = 0; l < L; l++) acc[jj][l] = 0.f;

    for (int it = 0; it < 16; it++) {
        int n2 = it * 64 + lane * 2;
        float2 pv[L];
        #pragma unroll
        for (int l = 0; l < L; l++) pv[l] = *(const float2*)&p_sm[l * 1024 + n2];
        #pragma unroll
        for (int jj = 0; jj < 4; jj++) {
            __half2 v2 = *(const __half2*)&vbase[(size_t)(wrp * 4 + jj) * NPIX + n2];
            float v0 = __low2float(v2), v1 = __high2float(v2);
            #pragma unroll
            for (int l = 0; l < L; l++) acc[jj][l] += v0 * pv[l].x + v1 * pv[l].y;
        }
    }
    #pragma unroll
    for (int jj = 0; jj < 4; jj++)
        #pragma unroll
        for (int l = 0; l < L; l++) {
            float v = acc[jj][l];
            #pragma unroll
            for (int o = 16; o; o >>= 1) v += __shfl_xor_sync(0xffffffffu, v, o);
            if (lane == 0)
                latpart[split * 65536 + bh * 1024 + (wrp * 4 + jj) * 16 + l] = v;
        }
}

// attn1d: reduce splits, compute sinv inline, scale -> latread. grid 256x256.
__global__ __launch_bounds__(256) void attn1d_kernel(
    const float* __restrict__ latpart, const float* __restrict__ lsum_g,
    float* __restrict__ latread)
{
    int e = blockIdx.x * 256 + threadIdx.x;
    int bh = e >> 10, rem = e & 1023, r = rem >> 4, l = rem & 15;
    float s = latpart[e] + latpart[65536 + e] + latpart[131072 + e] + latpart[196608 + e];
    float d = lsum_g[bh * 64 + l] + lsum_g[bh * 64 + 16 + l] +
              lsum_g[bh * 64 + 32 + l] + lsum_g[bh * 64 + 48 + l];
    int b = bh >> 3, h = bh & 7;
    latread[((size_t)b * C + h * DH + r) * L + l] = s / d;
}

// ---------------------------------------------------------------------------
// kvl: kvl[b] = w_kv_lat @ lat_read[b]; normalize k-part per (head,l).
// ---------------------------------------------------------------------------
__global__ __launch_bounds__(256) void kvl_kernel(
    const float* __restrict__ w_kv_lat, const float* __restrict__ latread,
    float* __restrict__ kvl)
{
    int b = blockIdx.x, c0 = blockIdx.y * 64;
    __shared__ float slat[C][L];
    __shared__ float stile[64][L];
    __shared__ float snorm[L];
    int tid = threadIdx.x;
    const float* lr = latread + (size_t)b * C * L;
    for (int i = tid; i < C * L; i += 256) slat[i >> 4][i & 15] = lr[i];
    __syncthreads();
    for (int p = tid; p < 64 * L; p += 256) {
        int j = p >> 4, l = p & 15;
        const float* wrow = w_kv_lat + (size_t)(c0 + j) * C;
        float acc = 0.f;
        for (int c2 = 0; c2 < C; c2++) acc += wrow[c2] * slat[c2][l];
        stile[j][l] = acc;
    }
    __syncthreads();
    if (c0 < C) {
        if (tid < L) {
            float s = 0.f;
            for (int j = 0; j < 64; j++) { float v = stile[j][tid]; s += v * v; }
            snorm[tid] = 1.f / fmaxf(sqrtf(s), EPSN);
        }
        __syncthreads();
        for (int p = tid; p < 64 * L; p += 256)
            kvl[((size_t)b * 2 * C + c0 + (p >> 4)) * L + (p & 15)] =
                stile[p >> 4][p & 15] * snorm[p & 15];
    } else {
        for (int p = tid; p < 64 * L; p += 256)
            kvl[((size_t)b * 2 * C + c0 + (p >> 4)) * L + (p & 15)] = stile[p >> 4][p & 15];
    }
}

// ---------------------------------------------------------------------------
// attn2: 2 pixels/thread via half2 q loads; fp16 xwT out.
// grid (16, HEADS, Bsz), 128 threads.
// ---------------------------------------------------------------------------
__global__ __launch_bounds__(128) void attn2_kernel(
    const __half* __restrict__ kvq, const float* __restrict__ kvl,
    __half* __restrict__ xwT)
{
    int b = blockIdx.z, h = blockIdx.y;
    int tid = threadIdx.x;
    int n = blockIdx.x * 256 + 2 * tid;
    __shared__ float skl[DH][L];
    __shared__ float svl[DH][L];
    __shared__ unsigned short sh[DH][256];

    const float* kvlb = kvl + (size_t)b * 2 * C * L;
    for (int i = tid; i < DH * L; i += 128) {
        skl[i >> 4][i & 15] = kvlb[(h * DH + (i >> 4)) * L + (i & 15)];
        svl[i >> 4][i & 15] = kvlb[(C + h * DH + (i >> 4)) * L + (i & 15)];
    }
    __syncthreads();

    const __half* qcol = kvq + ((size_t)b * MROWS + 1024 + h * DH) * NPIX + n;
    float dot[2][L], nrm[2] = {0.f, 0.f};
    #pragma unroll
    for (int i = 0; i < 2; i++)
        #pragma unroll
        for (int l = 0; l < L; l++) dot[i][l] = 0.f;
    for (int j = 0; j < DH; j++) {
        __half2 q2 = *(const __half2*)(qcol + (size_t)j * NPIX);
        float q0 = __low2float(q2), q1 = __high2float(q2);
        nrm[0] += q0 * q0; nrm[1] += q1 * q1;
        #pragma unroll
        for (int l = 0; l < L; l++) {
            float s = skl[j][l];
            dot[0][l] += q0 * s;
            dot[1][l] += q1 * s;
        }
    }
    float is[2];
    #pragma unroll
    for (int i = 0; i < 2; i++) {
        float inv = SCALE / fmaxf(sqrtf(nrm[i]), EPSN);
        float s = 0.f;
        #pragma unroll
        for (int l = 0; l < L; l++) { dot[i][l] = __expf(dot[i][l] * inv); s += dot[i][l]; }
        is[i] = 1.f / s;
    }

    for (int j = 0; j < DH; j++) {
        float a0 = 0.f, a1 = 0.f;
        #pragma unroll
        for (int l = 0; l < L; l++) {
            float v = svl[j][l];
            a0 += dot[0][l] * v;
            a1 += dot[1][l] * v;
        }
        sh[j][2 * tid]     = __half_as_ushort(__float2half_rn(a0 * is[0]));
        sh[j][2 * tid + 1] = __half_as_ushort(__float2half_rn(a1 * is[1]));
    }
    __syncthreads();

    #pragma unroll
    for (int px = 0; px < 2; px++) {
        int pp = 2 * tid + px;
        int np = blockIdx.x * 256 + pp;
        size_t base = ((size_t)b * NPIX + np) * C + h * DH;
        #pragma unroll
        for (int c4 = 0; c4 < 8; c4++) {
            uint32_t wv[4];
            #pragma unroll
            for (int k = 0; k < 4; k++) {
                int j = c4 * 8 + k * 2;
                wv[k] = (uint32_t)sh[j][pp] | ((uint32_t)sh[j + 1][pp] << 16);
            }
            *(uint4*)(xwT + base + c4 * 8) = make_uint4(wv[0], wv[1], wv[2], wv[3]);
        }
    }
}

// ---------------------------------------------------------------------------
// Launch: R8 topology (proven). One side stream for wp conv + qlhat; all
// tensor work and the attention chain serialized on the main stream.
// ---------------------------------------------------------------------------
extern "C" void kernel_launch(void* const* d_in, const int* in_sizes, int n_in,
                              void* d_out, int out_size)
{
    const float* x        = (const float*)d_in[0];
    const float* latents  = (const float*)d_in[1];
    const float* w_q_lat  = (const float*)d_in[2];
    const float* w_kv_x   = (const float*)d_in[3];
    const float* w_q_x    = (const float*)d_in[4];
    const float* w_kv_lat = (const float*)d_in[5];
    const float* w_proj   = (const float*)d_in[6];
    const float* b_proj   = (const float*)d_in[7];
    float* out = (float*)d_out;

    float *lsum, *latpart, *latread, *kvl, *qlhat;
    __half *kvq, *xT, *xwT, *wA, *wp;
    cudaGetSymbolAddress((void**)&kvq, g_kvq);
    cudaGetSymbolAddress((void**)&lsum, g_lsum);
    cudaGetSymbolAddress((void**)&latpart, g_latpart);
    cudaGetSymbolAddress((void**)&latread, g_latread);
    cudaGetSymbolAddress((void**)&kvl, g_kvl);
    cudaGetSymbolAddress((void**)&qlhat, g_qlhat);
    cudaGetSymbolAddress((void**)&xT, g_xT);
    cudaGetSymbolAddress((void**)&xwT, g_xwT);
    cudaGetSymbolAddress((void**)&wA, g_wA);
    cudaGetSymbolAddress((void**)&wp, g_wp);

    static cudaStream_t s1 = nullptr;
    static cudaEvent_t evFork = nullptr, evSide = nullptr;
    if (!s1) {
        cudaStreamCreateWithFlags(&s1, cudaStreamNonBlocking);
        cudaEventCreateWithFlags(&evFork, cudaEventDisableTiming);
        cudaEventCreateWithFlags(&evSide, cudaEventDisableTiming);
    }

    cudaFuncSetAttribute(gemm_mma, cudaFuncAttributeMaxDynamicSharedMemorySize, 3 * STG);
    int attn1_smem = (L * 1024 + DH * L + 16 * L) * sizeof(float);
    cudaFuncSetAttribute(attn1_fused_kernel, cudaFuncAttributeMaxDynamicSharedMemorySize, attn1_smem);

    // side stream: proj weight conversion + qlhat (consumed later)
    cudaEventRecord(evFork, 0);
    cudaStreamWaitEvent(s1, evFork, 0);
    wconv_kernel<<<(Q4 + 255) / 256, 256, 0, s1>>>(w_proj, wp, Q4);
    qlhat_kernel<<<HEADS, 256, 0, s1>>>(w_q_lat, latents, qlhat);
    cudaEventRecord(evSide, s1);

    // main chain
    wconvA_kernel<<<(KV4 + Q4 + 255) / 256, 256>>>(w_kv_x, w_q_x, wA);
    tconv_kernel<<<dim3(NPIX / 32, C / 64, Bsz), dim3(32, 8)>>>(x, xT);

    // fused kv+q GEMM (M=1536) -> fp16 kvq
    gemm_mma<<<dim3(32, 12, Bsz), 256, 3 * STG>>>(wA, xT, kvq, nullptr, nullptr, MROWS);

    // join side stream (qlhat needed by attn1, wp by final gemm)
    cudaStreamWaitEvent(0, evSide, 0);

    // latent read attention (fused exp + partial P@V)
    attn1_fused_kernel<<<dim3(64, 4), 512, attn1_smem>>>(kvq, qlhat, latpart, lsum);
    attn1d_kernel<<<256, 256>>>(latpart, lsum, latread);

    kvl_kernel<<<dim3(Bsz, 16), 256>>>(w_kv_lat, latread, kvl);

    // latent write attention -> fp16 xwT
    attn2_kernel<<<dim3(16, HEADS, Bsz), 128>>>(kvq, kvl, xwT);

    // output projection + bias (fp32 out)
    gemm_mma<<<dim3(32, 4, Bsz), 256, 3 * STG>>>(wp, xwT, nullptr, out, b_proj, C);
}